// round 1
// baseline (speedup 1.0000x reference)
#include <cuda_runtime.h>
#include <math.h>
#include <stdint.h>

// Problem constants (fixed by reference)
#define BATCH   64
#define PIX     196      // 14*14
#define ENC     2048
#define DEC     512
#define ATT     512
#define EMBD    512
#define VOC     10000
#define MAXLEN  52
#define TSTEPS  51       // MAXLEN-1
#define HCAT    4608     // 512 (dec_att) + 2048 (fbeta) + 2048 (hh)
#define XDIM    2560     // EMBD + ENC

// Output layout (flattened tuple, float32):
//   predictions (64,51,10000) | encoded_captions (64,52) | decode_len (64) | alphas (64,51,196)
#define PRED_OFF   0
#define CAP_OFF    32640000
#define LEN_OFF    32643328
#define ALPHA_OFF  32643392

// ---------------- scratch (__device__ globals; no allocation) ----------------
__device__ float g_Whcat[DEC * HCAT];      // [W_dec_att | W_fbeta | W_hh] : 512 x 4608
__device__ float g_bias_cat[HCAT];         // [b_dec_att | b_fbeta | 0]
__device__ float g_bias_ihhh[4 * DEC];     // b_ih + b_hh
__device__ float g_mask[TSTEPS * BATCH];   // step mask as float
__device__ float g_mean[BATCH * ENC];
__device__ float g_h[BATCH * DEC];
__device__ float g_c[BATCH * DEC];
__device__ float g_att_enc[BATCH * PIX * ATT];
__device__ float g_hproj[BATCH * HCAT];
__device__ float g_e[BATCH * PIX];
__device__ float g_alpha[BATCH * PIX];
__device__ float g_x[BATCH * XDIM];
__device__ float g_gates[BATCH * 4 * DEC];

__device__ __forceinline__ float sigmoidf_(float x) { return 1.f / (1.f + __expf(-x)); }

// ---------------- generic tiled fp32 GEMM: C = A(MxK) * B(KxN) [+bias][+addmat][*rowscale]
// BM=64, BN=64, BK=16, 256 threads, 4x4 per thread. K must be a multiple of 16.
__global__ void gemm64(const float* __restrict__ A, int lda,
                       const float* __restrict__ Bm, int ldb,
                       float* __restrict__ C, int ldc,
                       int M, int N, int K,
                       const float* __restrict__ bias,
                       const float* __restrict__ addmat, int ld_add,
                       const float* __restrict__ rowscale)
{
    __shared__ float As[16][64];
    __shared__ float Bs[16][64];

    const int m0 = blockIdx.y * 64;
    const int n0 = blockIdx.x * 64;
    const int tid = threadIdx.x;
    const int ty = tid >> 4;          // 0..15
    const int tx = tid & 15;          // 0..15

    const int ar = tid >> 2;          // 0..63  (A row in tile)
    const int ak = (tid & 3) * 4;     // 0,4,8,12
    const int bk = tid >> 4;          // 0..15
    const int bn = (tid & 15) * 4;    // 0..60

    float acc[4][4];
#pragma unroll
    for (int i = 0; i < 4; i++)
#pragma unroll
        for (int j = 0; j < 4; j++) acc[i][j] = 0.f;

    for (int k0 = 0; k0 < K; k0 += 16) {
        // load A tile (transposed into As[k][m])
        float4 av = make_float4(0.f, 0.f, 0.f, 0.f);
        if (m0 + ar < M)
            av = *(const float4*)&A[(size_t)(m0 + ar) * lda + k0 + ak];
        As[ak + 0][ar] = av.x;
        As[ak + 1][ar] = av.y;
        As[ak + 2][ar] = av.z;
        As[ak + 3][ar] = av.w;

        // load B tile
        float4 bv = make_float4(0.f, 0.f, 0.f, 0.f);
        if (n0 + bn + 3 < N) {
            bv = *(const float4*)&Bm[(size_t)(k0 + bk) * ldb + n0 + bn];
        } else {
            float* pv = (float*)&bv;
#pragma unroll
            for (int j = 0; j < 4; j++)
                if (n0 + bn + j < N) pv[j] = Bm[(size_t)(k0 + bk) * ldb + n0 + bn + j];
        }
        *(float4*)&Bs[bk][bn] = bv;

        __syncthreads();

#pragma unroll
        for (int kk = 0; kk < 16; kk++) {
            float4 a4 = *(const float4*)&As[kk][ty * 4];
            float4 b4 = *(const float4*)&Bs[kk][tx * 4];
            float aa[4] = {a4.x, a4.y, a4.z, a4.w};
            float bb[4] = {b4.x, b4.y, b4.z, b4.w};
#pragma unroll
            for (int i = 0; i < 4; i++)
#pragma unroll
                for (int j = 0; j < 4; j++)
                    acc[i][j] = fmaf(aa[i], bb[j], acc[i][j]);
        }
        __syncthreads();
    }

#pragma unroll
    for (int i = 0; i < 4; i++) {
        int m = m0 + ty * 4 + i;
        if (m >= M) continue;
        float rs = rowscale ? rowscale[m] : 1.f;
#pragma unroll
        for (int j = 0; j < 4; j++) {
            int n = n0 + tx * 4 + j;
            if (n >= N) continue;
            float v = acc[i][j];
            if (bias) v += bias[n];
            if (addmat) v += addmat[(size_t)m * ld_add + n];
            v *= rs;
            C[(size_t)m * ldc + n] = v;
        }
    }
}

// ---------------- prologue: weight concat, biases, masks, int outputs ----------------
__global__ void init_kernel(const float* __restrict__ Wdec, const float* __restrict__ Wfbeta,
                            const float* __restrict__ Whh,
                            const float* __restrict__ b_dec_att, const float* __restrict__ b_fbeta,
                            const float* __restrict__ b_ih, const float* __restrict__ b_hh,
                            const int* __restrict__ captions, const int* __restrict__ cap_len,
                            float* __restrict__ out)
{
    int idx = blockIdx.x * blockDim.x + threadIdx.x;
    int stride = gridDim.x * blockDim.x;
    const int total = DEC * HCAT;
    for (int i = idx; i < total; i += stride) {
        int k = i / HCAT, j = i - k * HCAT;
        float v;
        if (j < DEC)                v = Wdec[k * DEC + j];
        else if (j < DEC + ENC)     v = Wfbeta[k * ENC + (j - DEC)];
        else                        v = Whh[k * (4 * DEC) + (j - DEC - ENC)];
        g_Whcat[(size_t)k * HCAT + j] = v;
    }
    if (idx < HCAT) {
        float bv;
        if (idx < DEC)              bv = b_dec_att[idx];
        else if (idx < DEC + ENC)   bv = b_fbeta[idx - DEC];
        else                        bv = 0.f;
        g_bias_cat[idx] = bv;
    }
    if (idx < 4 * DEC) g_bias_ihhh[idx] = b_ih[idx] + b_hh[idx];
    if (idx < TSTEPS * BATCH) {
        int t = idx / BATCH, b = idx - t * BATCH;
        g_mask[idx] = (t < cap_len[b] - 1) ? 1.f : 0.f;
    }
    if (idx < BATCH * MAXLEN) out[CAP_OFF + idx] = (float)captions[idx];
    if (idx < BATCH)          out[LEN_OFF + idx] = (float)(cap_len[idx] - 1);
}

// ---------------- mean over pixels ----------------
__global__ void mean_kernel(const float* __restrict__ enc)
{
    int b = blockIdx.y;
    int d = blockIdx.x * 256 + threadIdx.x;
    const float* ep = enc + (size_t)b * PIX * ENC + d;
    float s = 0.f;
    for (int p = 0; p < PIX; p++) s += ep[(size_t)p * ENC];
    g_mean[b * ENC + d] = s * (1.f / (float)PIX);
}

// ---------------- attention scores: e[b,p] = sum_k tanh(att_enc+att_dec)*Wf + bf ----------------
__global__ void att_e_kernel(const float* __restrict__ att_enc,
                             const float* __restrict__ hproj,
                             const float* __restrict__ Wf,
                             const float* __restrict__ bf,
                             float* __restrict__ e)
{
    __shared__ float sdec[ATT];
    __shared__ float swf[ATT];
    int b = blockIdx.y;
    for (int k = threadIdx.x; k < ATT; k += blockDim.x) {
        sdec[k] = hproj[b * HCAT + k];   // includes b_dec_att via bias_cat
        swf[k] = Wf[k];
    }
    __syncthreads();
    int warp = threadIdx.x >> 5, lane = threadIdx.x & 31;
    int p = blockIdx.x * 4 + warp;
    if (p >= PIX) return;
    const float* ae = att_enc + ((size_t)(b * PIX + p)) * ATT;
    float acc = 0.f;
    for (int k = lane; k < ATT; k += 32)
        acc += tanhf(ae[k] + sdec[k]) * swf[k];
#pragma unroll
    for (int o = 16; o; o >>= 1) acc += __shfl_down_sync(0xffffffff, acc, o);
    if (lane == 0) e[b * PIX + p] = acc + bf[0];
}

// ---------------- softmax over pixels + masked alphas output ----------------
__global__ void softmax_kernel(const float* __restrict__ e, float* __restrict__ alpha,
                               float* __restrict__ alphas_out,
                               const int* __restrict__ cap_len, int t)
{
    __shared__ float red[256];
    int b = blockIdx.x, tid = threadIdx.x;
    float v = (tid < PIX) ? e[b * PIX + tid] : -1e30f;
    red[tid] = v; __syncthreads();
    for (int s = 128; s; s >>= 1) { if (tid < s) red[tid] = fmaxf(red[tid], red[tid + s]); __syncthreads(); }
    float mx = red[0]; __syncthreads();
    float ex = (tid < PIX) ? expf(v - mx) : 0.f;
    red[tid] = ex; __syncthreads();
    for (int s = 128; s; s >>= 1) { if (tid < s) red[tid] += red[tid + s]; __syncthreads(); }
    float inv = 1.f / red[0];
    if (tid < PIX) {
        float a = ex * inv;
        alpha[b * PIX + tid] = a;
        float m = (t < cap_len[b] - 1) ? 1.f : 0.f;
        alphas_out[(size_t)b * TSTEPS * PIX + (size_t)t * PIX + tid] = a * m;
    }
}

// ---------------- awe = gate * (alpha @ enc);  build x = [emb_t | awe] ----------------
__global__ void awe_x_kernel(const float* __restrict__ enc, const float* __restrict__ alpha,
                             const float* __restrict__ hproj, const float* __restrict__ emb,
                             const int* __restrict__ captions, int t,
                             float* __restrict__ x)
{
    int b = blockIdx.y;
    int chunk = blockIdx.x;
    int tid = threadIdx.x;
    if (chunk == 2) {
        int tok = captions[b * MAXLEN + t];
        for (int j = tid; j < EMBD; j += blockDim.x)
            x[b * XDIM + j] = emb[(size_t)tok * EMBD + j];
        return;
    }
    __shared__ float sa[PIX];
    if (tid < PIX) sa[tid] = alpha[b * PIX + tid];
    __syncthreads();
    int d = chunk * 1024 + tid * 4;
    float4 acc = make_float4(0.f, 0.f, 0.f, 0.f);
    const float* ep = enc + (size_t)b * PIX * ENC + d;
    for (int p = 0; p < PIX; p++) {
        float a = sa[p];
        float4 ev = *(const float4*)(ep + (size_t)p * ENC);
        acc.x = fmaf(a, ev.x, acc.x);
        acc.y = fmaf(a, ev.y, acc.y);
        acc.z = fmaf(a, ev.z, acc.z);
        acc.w = fmaf(a, ev.w, acc.w);
    }
    float4 g = *(const float4*)&hproj[b * HCAT + DEC + d];  // fbeta segment (bias included)
    g.x = sigmoidf_(g.x); g.y = sigmoidf_(g.y); g.z = sigmoidf_(g.z); g.w = sigmoidf_(g.w);
    float4 ov = make_float4(acc.x * g.x, acc.y * g.y, acc.z * g.z, acc.w * g.w);
    *(float4*)&x[b * XDIM + EMBD + d] = ov;
}

// ---------------- LSTM pointwise update (masked) ----------------
__global__ void lstm_kernel(const float* __restrict__ gates, const int* __restrict__ cap_len, int t)
{
    int b = blockIdx.x, j = threadIdx.x;
    if (t >= cap_len[b] - 1) return;   // masked: h,c unchanged
    float iv = gates[b * 2048 + j];
    float fv = gates[b * 2048 + 512 + j];
    float gv = gates[b * 2048 + 1024 + j];
    float ov = gates[b * 2048 + 1536 + j];
    float c_old = g_c[b * DEC + j];
    float cn = sigmoidf_(fv) * c_old + sigmoidf_(iv) * tanhf(gv);
    float hn = sigmoidf_(ov) * tanhf(cn);
    g_c[b * DEC + j] = cn;
    g_h[b * DEC + j] = hn;
}

// ---------------- host launcher ----------------
extern "C" void kernel_launch(void* const* d_in, const int* in_sizes, int n_in,
                              void* d_out, int out_size)
{
    const float* enc        = (const float*)d_in[0];
    const int*   captions   = (const int*)  d_in[1];
    const int*   cap_len    = (const int*)  d_in[2];
    const float* emb        = (const float*)d_in[3];
    const float* W_enc_att  = (const float*)d_in[4];
    const float* b_enc_att  = (const float*)d_in[5];
    const float* W_dec_att  = (const float*)d_in[6];
    const float* b_dec_att  = (const float*)d_in[7];
    const float* W_full_att = (const float*)d_in[8];
    const float* b_full_att = (const float*)d_in[9];
    const float* W_init_h   = (const float*)d_in[10];
    const float* b_init_h   = (const float*)d_in[11];
    const float* W_init_c   = (const float*)d_in[12];
    const float* b_init_c   = (const float*)d_in[13];
    const float* W_fbeta    = (const float*)d_in[14];
    // b_fbeta = d_in[15]
    const float* W_ih       = (const float*)d_in[16];
    const float* W_hh       = (const float*)d_in[17];
    const float* b_ih       = (const float*)d_in[18];
    const float* b_hh       = (const float*)d_in[19];
    const float* W_fc       = (const float*)d_in[20];
    const float* b_fc       = (const float*)d_in[21];
    const float* b_fbeta    = (const float*)d_in[15];
    float* out = (float*)d_out;

    float *pWhcat, *pbcat, *pbihh, *pmask, *pmean, *ph, *pc, *patt, *phproj, *pe, *palpha, *px, *pgates;
    cudaGetSymbolAddress((void**)&pWhcat, g_Whcat);
    cudaGetSymbolAddress((void**)&pbcat,  g_bias_cat);
    cudaGetSymbolAddress((void**)&pbihh,  g_bias_ihhh);
    cudaGetSymbolAddress((void**)&pmask,  g_mask);
    cudaGetSymbolAddress((void**)&pmean,  g_mean);
    cudaGetSymbolAddress((void**)&ph,     g_h);
    cudaGetSymbolAddress((void**)&pc,     g_c);
    cudaGetSymbolAddress((void**)&patt,   g_att_enc);
    cudaGetSymbolAddress((void**)&phproj, g_hproj);
    cudaGetSymbolAddress((void**)&pe,     g_e);
    cudaGetSymbolAddress((void**)&palpha, g_alpha);
    cudaGetSymbolAddress((void**)&px,     g_x);
    cudaGetSymbolAddress((void**)&pgates, g_gates);

    // prologue
    init_kernel<<<2048, 256>>>(W_dec_att, W_fbeta, W_hh, b_dec_att, b_fbeta,
                               b_ih, b_hh, captions, cap_len, out);
    mean_kernel<<<dim3(ENC / 256, BATCH), 256>>>(enc);
    // h0, c0
    gemm64<<<dim3(DEC / 64, 1), 256>>>(pmean, ENC, W_init_h, DEC, ph, DEC,
                                       BATCH, DEC, ENC, b_init_h, nullptr, 0, nullptr);
    gemm64<<<dim3(DEC / 64, 1), 256>>>(pmean, ENC, W_init_c, DEC, pc, DEC,
                                       BATCH, DEC, ENC, b_init_c, nullptr, 0, nullptr);
    // att_enc = enc @ W_enc_att + b  (12544 x 512, K=2048)
    gemm64<<<dim3(ATT / 64, (BATCH * PIX) / 64), 256>>>(enc, ENC, W_enc_att, ATT, patt, ATT,
                                                        BATCH * PIX, ATT, ENC, b_enc_att,
                                                        nullptr, 0, nullptr);

    for (int t = 0; t < TSTEPS; t++) {
        // hproj = h @ [W_dec_att|W_fbeta|W_hh] + [b_dec_att|b_fbeta|0]
        gemm64<<<dim3(HCAT / 64, 1), 256>>>(ph, DEC, pWhcat, HCAT, phproj, HCAT,
                                            BATCH, HCAT, DEC, pbcat, nullptr, 0, nullptr);
        att_e_kernel<<<dim3(PIX / 4, BATCH), 128>>>(patt, phproj, W_full_att, b_full_att, pe);
        softmax_kernel<<<BATCH, 256>>>(pe, palpha, out + ALPHA_OFF, cap_len, t);
        awe_x_kernel<<<dim3(3, BATCH), 256>>>(enc, palpha, phproj, emb, captions, t, px);
        // gates = x @ W_ih + (b_ih+b_hh) + hproj[:,2560:]
        gemm64<<<dim3((4 * DEC) / 64, 1), 256>>>(px, XDIM, W_ih, 4 * DEC, pgates, 4 * DEC,
                                                 BATCH, 4 * DEC, XDIM, pbihh,
                                                 phproj + (DEC + ENC), HCAT, nullptr);
        lstm_kernel<<<BATCH, DEC>>>(pgates, cap_len, t);
        // preds = (h @ W_fc + b_fc) * mask  -> out[b, t, :]
        gemm64<<<dim3((VOC + 63) / 64, 1), 256>>>(ph, DEC, W_fc, VOC,
                                                  out + PRED_OFF + (size_t)t * VOC,
                                                  TSTEPS * VOC,
                                                  BATCH, VOC, DEC, b_fc,
                                                  nullptr, 0, pmask + t * BATCH);
        (void)in_sizes; (void)n_in; (void)out_size;
    }
}

// round 2
// speedup vs baseline: 3.5441x; 3.5441x over previous
#include <cuda_runtime.h>
#include <math.h>
#include <stdint.h>

// Problem constants
#define BATCH   64
#define PIX     196
#define ENC     2048
#define DEC     512
#define ATT     512
#define EMBD    512
#define VOC     10000
#define MAXLEN  52
#define TSTEPS  51
#define HCAT    4608     // 512 dec_att | 2048 fbeta | 2048 hh
#define XDIM    2560     // EMBD + ENC

// Output layout (flattened tuple, float32)
#define PRED_OFF   0
#define CAP_OFF    32640000
#define LEN_OFF    32643328
#define ALPHA_OFF  32643392

#define HSPLIT 4
#define GSPLIT 8
#define ISPLIT 8

// ---------------- scratch ----------------
__device__ float g_Whcat[DEC * HCAT];          // [W_dec_att | W_fbeta | W_hh]
__device__ float g_Winit[ENC * 1024];          // [W_init_h | W_init_c]
__device__ float g_mask[TSTEPS * BATCH];
__device__ float g_mean[BATCH * ENC];
__device__ float g_hbuf[2][BATCH * DEC];
__device__ float g_c[BATCH * DEC];
__device__ float g_att_enc[BATCH * PIX * ATT];
__device__ float g_hpart[HSPLIT * BATCH * HCAT];
__device__ float g_gpart[GSPLIT * BATCH * 4 * DEC];
__device__ float g_ipart[ISPLIT * BATCH * 1024];
__device__ float g_alpha[BATCH * PIX];
__device__ float g_x[BATCH * XDIM];

__device__ __forceinline__ float sigmoidf_(float x) { return 1.f / (1.f + __expf(-x)); }
__device__ __forceinline__ float tanh_fast(float x) {
    float y; asm("tanh.approx.f32 %0, %1;" : "=f"(y) : "f"(x)); return y;
}

// ---------------- GEMM: BM=64, BN=128, BK=16, 256 thr, 8x4/thread, double-buffered
// C = A(64|M x Kc) * B(Kc x N) per blockIdx.z chunk. If gridDim.z>1: store raw
// partial at C + z*64*ldc (ldc==N). Else: +bias, *rowscale, store.
__global__ void __launch_bounds__(256)
gemm_k(const float* __restrict__ A, int lda,
       const float* __restrict__ B, int ldb,
       float* __restrict__ C, int ldc,
       int N, int Kc,
       const float* __restrict__ bias,
       const float* __restrict__ rowscale)
{
    __shared__ float As[2][16][64];
    __shared__ float Bs[2][16][128];

    const int tid = threadIdx.x;
    const int m0 = blockIdx.y * 64;
    const int n0 = blockIdx.x * 128;
    const int koff = blockIdx.z * Kc;

    const int ty  = tid >> 5;         // 0..7  row group (per-warp constant)
    const int tx  = tid & 31;         // 0..31 col group
    const int ar  = tid >> 2;         // 0..63 A row
    const int akc = (tid & 3) * 4;    // 0,4,8,12 A k
    const int bkr = tid >> 4;         // 0..15 B k-row
    const int bnc = (tid & 15) * 8;   // 0..120 B col

    const float* Aptr = A + (size_t)(m0 + ar) * lda + koff + akc;
    const float* Bptr = B + (size_t)(koff + bkr) * ldb + n0 + bnc;
    const size_t bstep = (size_t)16 * ldb;
    const bool nfull = (n0 + 128) <= N;

    const int nk = Kc >> 4;

    float4 aR, bR0, bR1;

    // prologue load (kt = 0)
    aR = *(const float4*)Aptr;
    if (nfull) {
        bR0 = *(const float4*)Bptr;
        bR1 = *(const float4*)(Bptr + 4);
    } else {
        float t0[4] = {0,0,0,0}, t1[4] = {0,0,0,0};
#pragma unroll
        for (int j = 0; j < 4; j++) {
            if (n0 + bnc + j     < N) t0[j] = Bptr[j];
            if (n0 + bnc + 4 + j < N) t1[j] = Bptr[4 + j];
        }
        bR0 = make_float4(t0[0],t0[1],t0[2],t0[3]);
        bR1 = make_float4(t1[0],t1[1],t1[2],t1[3]);
    }
    As[0][akc+0][ar] = aR.x; As[0][akc+1][ar] = aR.y;
    As[0][akc+2][ar] = aR.z; As[0][akc+3][ar] = aR.w;
    *(float4*)&Bs[0][bkr][bnc]   = bR0;
    *(float4*)&Bs[0][bkr][bnc+4] = bR1;
    __syncthreads();

    float acc[8][4];
#pragma unroll
    for (int i = 0; i < 8; i++)
#pragma unroll
        for (int j = 0; j < 4; j++) acc[i][j] = 0.f;

    for (int kt = 0; kt < nk; kt++) {
        const int cur = kt & 1, nxt = cur ^ 1;
        if (kt + 1 < nk) {
            aR = *(const float4*)(Aptr + (kt + 1) * 16);
            const float* bp = Bptr + (size_t)(kt + 1) * bstep;
            if (nfull) {
                bR0 = *(const float4*)bp;
                bR1 = *(const float4*)(bp + 4);
            } else {
                float t0[4] = {0,0,0,0}, t1[4] = {0,0,0,0};
#pragma unroll
                for (int j = 0; j < 4; j++) {
                    if (n0 + bnc + j     < N) t0[j] = bp[j];
                    if (n0 + bnc + 4 + j < N) t1[j] = bp[4 + j];
                }
                bR0 = make_float4(t0[0],t0[1],t0[2],t0[3]);
                bR1 = make_float4(t1[0],t1[1],t1[2],t1[3]);
            }
        }
#pragma unroll
        for (int kk = 0; kk < 16; kk++) {
            float4 a0 = *(const float4*)&As[cur][kk][ty * 8];
            float4 a1 = *(const float4*)&As[cur][kk][ty * 8 + 4];
            float4 b  = *(const float4*)&Bs[cur][kk][tx * 4];
            float av[8] = {a0.x,a0.y,a0.z,a0.w,a1.x,a1.y,a1.z,a1.w};
            float bv[4] = {b.x,b.y,b.z,b.w};
#pragma unroll
            for (int i = 0; i < 8; i++)
#pragma unroll
                for (int j = 0; j < 4; j++)
                    acc[i][j] = fmaf(av[i], bv[j], acc[i][j]);
        }
        if (kt + 1 < nk) {
            As[nxt][akc+0][ar] = aR.x; As[nxt][akc+1][ar] = aR.y;
            As[nxt][akc+2][ar] = aR.z; As[nxt][akc+3][ar] = aR.w;
            *(float4*)&Bs[nxt][bkr][bnc]   = bR0;
            *(float4*)&Bs[nxt][bkr][bnc+4] = bR1;
            __syncthreads();
        }
    }

    // epilogue
    const bool split = (gridDim.z > 1);
    float* Co = C + (split ? (size_t)blockIdx.z * 64 * ldc : 0);
#pragma unroll
    for (int i = 0; i < 8; i++) {
        const int gm = m0 + ty * 8 + i;
        float* crow = Co + (size_t)gm * ldc;
        const int gn = n0 + tx * 4;
        if (gn + 4 > N) {
#pragma unroll
            for (int j = 0; j < 4; j++) {
                if (gn + j < N) {
                    float v = acc[i][j];
                    if (!split) {
                        if (bias) v += bias[gn + j];
                        if (rowscale) v *= rowscale[gm];
                    }
                    crow[gn + j] = v;
                }
            }
        } else {
            float4 v = make_float4(acc[i][0], acc[i][1], acc[i][2], acc[i][3]);
            if (!split) {
                if (bias) {
                    v.x += bias[gn]; v.y += bias[gn+1]; v.z += bias[gn+2]; v.w += bias[gn+3];
                }
                if (rowscale) {
                    float rs = rowscale[gm];
                    v.x *= rs; v.y *= rs; v.z *= rs; v.w *= rs;
                }
            }
            *(float4*)&crow[gn] = v;
        }
    }
}

// ---------------- init: weight concats, mask, int outputs ----------------
__global__ void init_kernel(const float* __restrict__ Wdec, const float* __restrict__ Wfbeta,
                            const float* __restrict__ Whh,
                            const float* __restrict__ Wih_unused,
                            const float* __restrict__ Winith, const float* __restrict__ Winitc,
                            const int* __restrict__ captions, const int* __restrict__ cap_len,
                            float* __restrict__ out)
{
    int idx = blockIdx.x * blockDim.x + threadIdx.x;
    int stride = gridDim.x * blockDim.x;
    // Whcat: 512 x 4608
    for (int i = idx; i < DEC * HCAT; i += stride) {
        int k = i / HCAT, j = i - k * HCAT;
        float v;
        if (j < DEC)              v = Wdec[k * DEC + j];
        else if (j < DEC + ENC)   v = Wfbeta[k * ENC + (j - DEC)];
        else                      v = Whh[k * (4 * DEC) + (j - DEC - ENC)];
        g_Whcat[i] = v;
    }
    // Winit: 2048 x 1024
    for (int i = idx; i < ENC * 1024; i += stride) {
        int k = i >> 10, j = i & 1023;
        g_Winit[i] = (j < DEC) ? Winith[k * DEC + j] : Winitc[k * DEC + (j - DEC)];
    }
    if (idx < TSTEPS * BATCH) {
        int t = idx / BATCH, b = idx - t * BATCH;
        g_mask[idx] = (t < cap_len[b] - 1) ? 1.f : 0.f;
    }
    if (idx < BATCH * MAXLEN) out[CAP_OFF + idx] = (float)captions[idx];
    if (idx < BATCH)          out[LEN_OFF + idx] = (float)(cap_len[idx] - 1);
}

// ---------------- mean over pixels ----------------
__global__ void mean_kernel(const float* __restrict__ enc)
{
    int b = blockIdx.y;
    int d = blockIdx.x * 256 + threadIdx.x;
    const float* ep = enc + (size_t)b * PIX * ENC + d;
    float s = 0.f;
    for (int p = 0; p < PIX; p++) s += ep[(size_t)p * ENC];
    g_mean[b * ENC + d] = s * (1.f / (float)PIX);
}

// ---------------- reduce init partials -> h0 (buf 1), c0 ----------------
__global__ void ireduce_kernel(const float* __restrict__ b_init_h,
                               const float* __restrict__ b_init_c)
{
    int idx = blockIdx.x * 256 + threadIdx.x;   // 64*1024
    int b = idx >> 10, col = idx & 1023;
    float v = 0.f;
#pragma unroll
    for (int z = 0; z < ISPLIT; z++) v += g_ipart[(size_t)(z * BATCH + b) * 1024 + col];
    if (col < DEC) g_hbuf[1][b * DEC + col] = v + b_init_h[col];
    else           g_c[b * DEC + (col - DEC)] = v + b_init_c[col - DEC];
}

// ---------------- fused attention scores + softmax (reduces hproj partials) --------
__global__ void att_softmax_kernel(const float* __restrict__ att_enc,
                                   const float* __restrict__ hpart,
                                   const float* __restrict__ b_dec_att,
                                   const float* __restrict__ Wf,
                                   const float* __restrict__ bf,
                                   const int* __restrict__ cap_len, int t,
                                   float* __restrict__ alpha,
                                   float* __restrict__ alphas_out)
{
    __shared__ float sdec[ATT];
    __shared__ float swf[ATT];
    __shared__ float se[256];
    __shared__ float red[256];
    const int b = blockIdx.x, tid = threadIdx.x;

    for (int k = tid; k < ATT; k += 256) {
        float s = b_dec_att[k];
#pragma unroll
        for (int z = 0; z < HSPLIT; z++) s += hpart[(size_t)(z * BATCH + b) * HCAT + k];
        sdec[k] = s;
        swf[k] = Wf[k];
    }
    se[tid] = -1e30f;
    __syncthreads();

    const int warp = tid >> 5, lane = tid & 31;
    const float bf0 = bf[0];
    for (int p = warp; p < PIX; p += 8) {
        const float* ae = att_enc + ((size_t)(b * PIX + p)) * ATT;
        float acc = 0.f;
        for (int k = lane; k < ATT; k += 32)
            acc += tanh_fast(ae[k] + sdec[k]) * swf[k];
#pragma unroll
        for (int o = 16; o; o >>= 1) acc += __shfl_down_sync(0xffffffffu, acc, o);
        if (lane == 0) se[p] = acc + bf0;
    }
    __syncthreads();

    red[tid] = se[tid]; __syncthreads();
    for (int s = 128; s; s >>= 1) { if (tid < s) red[tid] = fmaxf(red[tid], red[tid + s]); __syncthreads(); }
    float mx = red[0]; __syncthreads();
    float ex = (tid < PIX) ? __expf(se[tid] - mx) : 0.f;
    red[tid] = ex; __syncthreads();
    for (int s = 128; s; s >>= 1) { if (tid < s) red[tid] += red[tid + s]; __syncthreads(); }
    float inv = 1.f / red[0];
    if (tid < PIX) {
        float a = ex * inv;
        alpha[b * PIX + tid] = a;
        float m = (t < cap_len[b] - 1) ? 1.f : 0.f;
        alphas_out[(size_t)b * TSTEPS * PIX + (size_t)t * PIX + tid] = a * m;
    }
}

// ---------------- awe = sigmoid(fbeta_proj) * (alpha @ enc); x = [emb_t | awe] ------
__global__ void awe_x_kernel(const float* __restrict__ enc, const float* __restrict__ alpha,
                             const float* __restrict__ hpart, const float* __restrict__ b_fbeta,
                             const float* __restrict__ emb, const int* __restrict__ captions,
                             int t, float* __restrict__ x)
{
    const int b = blockIdx.y, chunk = blockIdx.x, tid = threadIdx.x;
    if (chunk == 2) {
        if (tid < 128) {
            int tok = captions[b * MAXLEN + t];
            *(float4*)&x[b * XDIM + tid * 4] = *(const float4*)&emb[(size_t)tok * EMBD + tid * 4];
        }
        return;
    }
    __shared__ float sa[PIX];
    if (tid < PIX) sa[tid] = alpha[b * PIX + tid];
    __syncthreads();
    const int d = chunk * 1024 + tid * 4;
    float4 acc0 = make_float4(0,0,0,0), acc1 = make_float4(0,0,0,0);
    const float* ep = enc + (size_t)b * PIX * ENC + d;
#pragma unroll 2
    for (int p = 0; p < PIX; p += 2) {
        float a0 = sa[p], a1 = sa[p + 1];
        float4 e0 = *(const float4*)(ep + (size_t)p * ENC);
        float4 e1 = *(const float4*)(ep + (size_t)(p + 1) * ENC);
        acc0.x = fmaf(a0, e0.x, acc0.x); acc0.y = fmaf(a0, e0.y, acc0.y);
        acc0.z = fmaf(a0, e0.z, acc0.z); acc0.w = fmaf(a0, e0.w, acc0.w);
        acc1.x = fmaf(a1, e1.x, acc1.x); acc1.y = fmaf(a1, e1.y, acc1.y);
        acc1.z = fmaf(a1, e1.z, acc1.z); acc1.w = fmaf(a1, e1.w, acc1.w);
    }
    float4 aw = make_float4(acc0.x + acc1.x, acc0.y + acc1.y, acc0.z + acc1.z, acc0.w + acc1.w);
    // gate = sigmoid(hproj fbeta segment + b_fbeta) (reduce partials)
    float4 g = make_float4(b_fbeta[d], b_fbeta[d+1], b_fbeta[d+2], b_fbeta[d+3]);
#pragma unroll
    for (int z = 0; z < HSPLIT; z++) {
        float4 p4 = *(const float4*)&hpart[(size_t)(z * BATCH + b) * HCAT + DEC + d];
        g.x += p4.x; g.y += p4.y; g.z += p4.z; g.w += p4.w;
    }
    g.x = sigmoidf_(g.x); g.y = sigmoidf_(g.y); g.z = sigmoidf_(g.z); g.w = sigmoidf_(g.w);
    float4 ov = make_float4(aw.x * g.x, aw.y * g.y, aw.z * g.z, aw.w * g.w);
    *(float4*)&x[b * XDIM + EMBD + d] = ov;
}

// ---------------- LSTM update (fuses gates partial-reduce + hh segment + biases) ----
__global__ void lstm_kernel(const float* __restrict__ gpart, const float* __restrict__ hpart,
                            const float* __restrict__ b_ih, const float* __restrict__ b_hh,
                            const int* __restrict__ cap_len, int t,
                            const float* __restrict__ hprev, float* __restrict__ hnew)
{
    const int b = blockIdx.x, j = threadIdx.x;
    float gv[4];
#pragma unroll
    for (int s = 0; s < 4; s++) {
        const int col = s * DEC + j;
        float v = b_ih[col] + b_hh[col];
#pragma unroll
        for (int z = 0; z < GSPLIT; z++) v += gpart[(size_t)(z * BATCH + b) * (4 * DEC) + col];
#pragma unroll
        for (int z = 0; z < HSPLIT; z++) v += hpart[(size_t)(z * BATCH + b) * HCAT + (DEC + ENC) + col];
        gv[s] = v;
    }
    const float hp = hprev[b * DEC + j];
    if (t < cap_len[b] - 1) {
        float c_old = g_c[b * DEC + j];
        float cn = sigmoidf_(gv[1]) * c_old + sigmoidf_(gv[0]) * tanhf(gv[2]);
        g_c[b * DEC + j] = cn;
        hnew[b * DEC + j] = sigmoidf_(gv[3]) * tanhf(cn);
    } else {
        hnew[b * DEC + j] = hp;
    }
}

// ---------------- host launcher ----------------
extern "C" void kernel_launch(void* const* d_in, const int* in_sizes, int n_in,
                              void* d_out, int out_size)
{
    const float* enc        = (const float*)d_in[0];
    const int*   captions   = (const int*)  d_in[1];
    const int*   cap_len    = (const int*)  d_in[2];
    const float* emb        = (const float*)d_in[3];
    const float* W_enc_att  = (const float*)d_in[4];
    const float* b_enc_att  = (const float*)d_in[5];
    const float* W_dec_att  = (const float*)d_in[6];
    const float* b_dec_att  = (const float*)d_in[7];
    const float* W_full_att = (const float*)d_in[8];
    const float* b_full_att = (const float*)d_in[9];
    const float* W_init_h   = (const float*)d_in[10];
    const float* b_init_h   = (const float*)d_in[11];
    const float* W_init_c   = (const float*)d_in[12];
    const float* b_init_c   = (const float*)d_in[13];
    const float* W_fbeta    = (const float*)d_in[14];
    const float* b_fbeta    = (const float*)d_in[15];
    const float* W_ih       = (const float*)d_in[16];
    const float* W_hh       = (const float*)d_in[17];
    const float* b_ih       = (const float*)d_in[18];
    const float* b_hh       = (const float*)d_in[19];
    const float* W_fc       = (const float*)d_in[20];
    const float* b_fc       = (const float*)d_in[21];
    float* out = (float*)d_out;
    (void)in_sizes; (void)n_in; (void)out_size;

    float *pWhcat, *pWinit, *pmask, *pmean, *phb0, *phb1, *patt, *php, *pgp, *pip, *palpha, *px;
    cudaGetSymbolAddress((void**)&pWhcat, g_Whcat);
    cudaGetSymbolAddress((void**)&pWinit, g_Winit);
    cudaGetSymbolAddress((void**)&pmask,  g_mask);
    cudaGetSymbolAddress((void**)&pmean,  g_mean);
    cudaGetSymbolAddress((void**)&phb0,   g_hbuf);
    phb1 = phb0 + BATCH * DEC;
    cudaGetSymbolAddress((void**)&patt,   g_att_enc);
    cudaGetSymbolAddress((void**)&php,    g_hpart);
    cudaGetSymbolAddress((void**)&pgp,    g_gpart);
    cudaGetSymbolAddress((void**)&pip,    g_ipart);
    cudaGetSymbolAddress((void**)&palpha, g_alpha);
    cudaGetSymbolAddress((void**)&px,     g_x);
    float* hbuf[2] = {phb0, phb1};

    // one-time stream/event setup (object creation only; identical launch graph every call)
    static cudaStream_t s2 = nullptr;
    static cudaEvent_t evH = nullptr, evP0 = nullptr, evP1 = nullptr;
    if (!s2) {
        cudaStreamCreateWithFlags(&s2, cudaStreamNonBlocking);
        cudaEventCreateWithFlags(&evH,  cudaEventDisableTiming);
        cudaEventCreateWithFlags(&evP0, cudaEventDisableTiming);
        cudaEventCreateWithFlags(&evP1, cudaEventDisableTiming);
    }
    cudaEvent_t evP[2] = {evP0, evP1};

    // ---- prologue ----
    init_kernel<<<2048, 256>>>(W_dec_att, W_fbeta, W_hh, W_ih, W_init_h, W_init_c,
                               captions, cap_len, out);
    mean_kernel<<<dim3(ENC / 256, BATCH), 256>>>(enc);
    // [h0|c0] partials: mean(64x2048) @ Winit(2048x1024), split-K 8
    gemm_k<<<dim3(8, 1, ISPLIT), 256>>>(pmean, ENC, pWinit, 1024, pip, 1024,
                                        1024, ENC / ISPLIT, nullptr, nullptr);
    ireduce_kernel<<<(BATCH * 1024) / 256, 256>>>(b_init_h, b_init_c);
    // att_enc = enc @ W_enc_att + b : (12544 x 512), K=2048
    gemm_k<<<dim3(ATT / 128, (BATCH * PIX) / 64, 1), 256>>>(enc, ENC, W_enc_att, ATT,
                                                            patt, ATT, ATT, ENC,
                                                            b_enc_att, nullptr);

    // ---- decode loop ----
    for (int t = 0; t < TSTEPS; t++) {
        const float* hprev = hbuf[(t + 1) & 1];
        float* hnew = hbuf[t & 1];

        // hproj partials: h_prev @ Whcat (64 x 4608), split-K 4
        gemm_k<<<dim3(HCAT / 128, 1, HSPLIT), 256>>>(hprev, DEC, pWhcat, HCAT, php, HCAT,
                                                     HCAT, DEC / HSPLIT, nullptr, nullptr);
        att_softmax_kernel<<<BATCH, 256>>>(patt, php, b_dec_att, W_full_att, b_full_att,
                                           cap_len, t, palpha, out + ALPHA_OFF);
        awe_x_kernel<<<dim3(3, BATCH), 256>>>(enc, palpha, php, b_fbeta, emb, captions, t, px);
        // gates partials: x @ W_ih (64 x 2048), split-K 8 (K=2560)
        gemm_k<<<dim3((4 * DEC) / 128, 1, GSPLIT), 256>>>(px, XDIM, W_ih, 4 * DEC, pgp, 4 * DEC,
                                                          4 * DEC, XDIM / GSPLIT, nullptr, nullptr);
        // hnew buffer was read by preds(t-2); make sure that read finished
        if (t >= 2) cudaStreamWaitEvent(0, evP[t & 1], 0);
        lstm_kernel<<<BATCH, DEC>>>(pgp, php, b_ih, b_hh, cap_len, t, hprev, hnew);

        // preds on side stream: (h_t @ W_fc + b_fc) * mask
        cudaEventRecord(evH, 0);
        cudaStreamWaitEvent(s2, evH, 0);
        gemm_k<<<dim3((VOC + 127) / 128, 1, 1), 256, 0, s2>>>(
            hnew, DEC, W_fc, VOC,
            out + PRED_OFF + (size_t)t * VOC, TSTEPS * VOC,
            VOC, DEC, b_fc, pmask + t * BATCH);
        cudaEventRecord(evP[t & 1], s2);
    }
    // join side stream back into origin stream
    cudaStreamWaitEvent(0, evP[0], 0);
    cudaStreamWaitEvent(0, evP[1], 0);
}

// round 3
// speedup vs baseline: 3.5738x; 1.0084x over previous
#include <cuda_runtime.h>
#include <cuda_fp16.h>
#include <math.h>
#include <stdint.h>

// Problem constants
#define BATCH   64
#define PIX     196
#define ENC     2048
#define DEC     512
#define ATT     512
#define EMBD    512
#define VOC     10000
#define MAXLEN  52
#define TSTEPS  51
#define HCAT    4608     // 512 dec_att | 2048 fbeta | 2048 hh
#define XDIM    2560     // EMBD + ENC

// Output layout (flattened tuple, float32)
#define PRED_OFF   0
#define CAP_OFF    32640000
#define LEN_OFF    32643328
#define ALPHA_OFF  32643392

#define HSPLIT 8
#define GSPLIT 16
#define ISPLIT 8

// ---------------- scratch ----------------
__device__ float  g_Whcat[DEC * HCAT];          // [W_dec_att | W_fbeta | W_hh] fp32
__device__ float  g_Winit[ENC * 1024];          // [W_init_h | W_init_c]
__device__ __half g_enc_h[BATCH * PIX * ENC];   // fp16 copy of enc (awe path)
__device__ __half g_Wfc_h[DEC * VOC];           // fp16 copy of W_fc
__device__ float  g_mask[TSTEPS * BATCH];
__device__ float  g_mean[BATCH * ENC];
__device__ float  g_hbuf[2][BATCH * DEC];
__device__ float  g_c[BATCH * DEC];
__device__ float  g_att_enc[BATCH * PIX * ATT];
__device__ float  g_hpart[HSPLIT * BATCH * HCAT];
__device__ float  g_gpart[GSPLIT * BATCH * 4 * DEC];
__device__ float  g_ipart[ISPLIT * BATCH * 1024];
__device__ float  g_alpha[BATCH * PIX];
__device__ float  g_x[BATCH * XDIM];

__device__ __forceinline__ float sigmoidf_(float x) { return 1.f / (1.f + __expf(-x)); }
__device__ __forceinline__ float tanh_fast(float x) {
    float y; asm("tanh.approx.f32 %0, %1;" : "=f"(y) : "f"(x)); return y;
}

// -------- B-operand loaders (fp32 / fp16 overloads) --------
__device__ __forceinline__ void load_b8(const float* p, float4& b0, float4& b1) {
    b0 = *(const float4*)p;
    b1 = *(const float4*)(p + 4);
}
__device__ __forceinline__ void load_b8(const __half* p, float4& b0, float4& b1) {
    uint4 r = *(const uint4*)p;
    const __half2* h = (const __half2*)&r;
    b0 = make_float4(__low2float(h[0]), __high2float(h[0]),
                     __low2float(h[1]), __high2float(h[1]));
    b1 = make_float4(__low2float(h[2]), __high2float(h[2]),
                     __low2float(h[3]), __high2float(h[3]));
}
__device__ __forceinline__ float b_elem(const float* p)  { return *p; }
__device__ __forceinline__ float b_elem(const __half* p) { return __half2float(*p); }

// ---------------- GEMM: BM=64, BN=128, BK=16, 256 thr, 8x4/thread, double-buffered
// C = A(64 x Kc) * B(Kc x N) per blockIdx.z chunk. If gridDim.z>1: raw partial at
// C + z*64*ldc. Else: +bias, *rowscale.
template <typename TB>
__global__ void __launch_bounds__(256)
gemm_k(const float* __restrict__ A, int lda,
       const TB* __restrict__ B, int ldb,
       float* __restrict__ C, int ldc,
       int N, int Kc,
       const float* __restrict__ bias,
       const float* __restrict__ rowscale)
{
    __shared__ float As[2][16][64];
    __shared__ float Bs[2][16][128];

    const int tid = threadIdx.x;
    const int m0 = blockIdx.y * 64;
    const int n0 = blockIdx.x * 128;
    const int koff = blockIdx.z * Kc;

    const int ty  = tid >> 5;         // 0..7
    const int tx  = tid & 31;         // 0..31
    const int ar  = tid >> 2;         // 0..63 A row
    const int akc = (tid & 3) * 4;    // A k
    const int bkr = tid >> 4;         // 0..15 B k-row
    const int bnc = (tid & 15) * 8;   // 0..120 B col

    const float* Aptr = A + (size_t)(m0 + ar) * lda + koff + akc;
    const TB*    Bptr = B + (size_t)(koff + bkr) * ldb + n0 + bnc;
    const size_t bstep = (size_t)16 * ldb;
    const bool nfull = (n0 + 128) <= N;

    const int nk = Kc >> 4;

    float4 aR, bR0, bR1;

    // prologue load
    aR = *(const float4*)Aptr;
    if (nfull) {
        load_b8(Bptr, bR0, bR1);
    } else {
        float t0[4] = {0,0,0,0}, t1[4] = {0,0,0,0};
#pragma unroll
        for (int j = 0; j < 4; j++) {
            if (n0 + bnc + j     < N) t0[j] = b_elem(Bptr + j);
            if (n0 + bnc + 4 + j < N) t1[j] = b_elem(Bptr + 4 + j);
        }
        bR0 = make_float4(t0[0],t0[1],t0[2],t0[3]);
        bR1 = make_float4(t1[0],t1[1],t1[2],t1[3]);
    }
    As[0][akc+0][ar] = aR.x; As[0][akc+1][ar] = aR.y;
    As[0][akc+2][ar] = aR.z; As[0][akc+3][ar] = aR.w;
    *(float4*)&Bs[0][bkr][bnc]   = bR0;
    *(float4*)&Bs[0][bkr][bnc+4] = bR1;
    __syncthreads();

    float acc[8][4];
#pragma unroll
    for (int i = 0; i < 8; i++)
#pragma unroll
        for (int j = 0; j < 4; j++) acc[i][j] = 0.f;

    for (int kt = 0; kt < nk; kt++) {
        const int cur = kt & 1, nxt = cur ^ 1;
        if (kt + 1 < nk) {
            aR = *(const float4*)(Aptr + (kt + 1) * 16);
            const TB* bp = Bptr + (size_t)(kt + 1) * bstep;
            if (nfull) {
                load_b8(bp, bR0, bR1);
            } else {
                float t0[4] = {0,0,0,0}, t1[4] = {0,0,0,0};
#pragma unroll
                for (int j = 0; j < 4; j++) {
                    if (n0 + bnc + j     < N) t0[j] = b_elem(bp + j);
                    if (n0 + bnc + 4 + j < N) t1[j] = b_elem(bp + 4 + j);
                }
                bR0 = make_float4(t0[0],t0[1],t0[2],t0[3]);
                bR1 = make_float4(t1[0],t1[1],t1[2],t1[3]);
            }
        }
#pragma unroll
        for (int kk = 0; kk < 16; kk++) {
            float4 a0 = *(const float4*)&As[cur][kk][ty * 8];
            float4 a1 = *(const float4*)&As[cur][kk][ty * 8 + 4];
            float4 b  = *(const float4*)&Bs[cur][kk][tx * 4];
            float av[8] = {a0.x,a0.y,a0.z,a0.w,a1.x,a1.y,a1.z,a1.w};
            float bv[4] = {b.x,b.y,b.z,b.w};
#pragma unroll
            for (int i = 0; i < 8; i++)
#pragma unroll
                for (int j = 0; j < 4; j++)
                    acc[i][j] = fmaf(av[i], bv[j], acc[i][j]);
        }
        if (kt + 1 < nk) {
            As[nxt][akc+0][ar] = aR.x; As[nxt][akc+1][ar] = aR.y;
            As[nxt][akc+2][ar] = aR.z; As[nxt][akc+3][ar] = aR.w;
            *(float4*)&Bs[nxt][bkr][bnc]   = bR0;
            *(float4*)&Bs[nxt][bkr][bnc+4] = bR1;
            __syncthreads();
        }
    }

    const bool split = (gridDim.z > 1);
    float* Co = C + (split ? (size_t)blockIdx.z * 64 * ldc : 0);
#pragma unroll
    for (int i = 0; i < 8; i++) {
        const int gm = m0 + ty * 8 + i;
        float* crow = Co + (size_t)gm * ldc;
        const int gn = n0 + tx * 4;
        if (gn + 4 > N) {
#pragma unroll
            for (int j = 0; j < 4; j++) {
                if (gn + j < N) {
                    float v = acc[i][j];
                    if (!split) {
                        if (bias) v += bias[gn + j];
                        if (rowscale) v *= rowscale[gm];
                    }
                    crow[gn + j] = v;
                }
            }
        } else {
            float4 v = make_float4(acc[i][0], acc[i][1], acc[i][2], acc[i][3]);
            if (!split) {
                if (bias) {
                    v.x += bias[gn]; v.y += bias[gn+1]; v.z += bias[gn+2]; v.w += bias[gn+3];
                }
                if (rowscale) {
                    float rs = rowscale[gm];
                    v.x *= rs; v.y *= rs; v.z *= rs; v.w *= rs;
                }
            }
            *(float4*)&crow[gn] = v;
        }
    }
}

// ---------------- init: weight concats, fp16 conversions, mask, int outputs --------
__global__ void init_kernel(const float* __restrict__ Wdec, const float* __restrict__ Wfbeta,
                            const float* __restrict__ Whh,
                            const float* __restrict__ Winith, const float* __restrict__ Winitc,
                            const float* __restrict__ Wfc, const float* __restrict__ enc,
                            const int* __restrict__ captions, const int* __restrict__ cap_len,
                            float* __restrict__ out)
{
    int idx = blockIdx.x * blockDim.x + threadIdx.x;
    int stride = gridDim.x * blockDim.x;
    for (int i = idx; i < DEC * HCAT; i += stride) {
        int k = i / HCAT, j = i - k * HCAT;
        float v;
        if (j < DEC)              v = Wdec[k * DEC + j];
        else if (j < DEC + ENC)   v = Wfbeta[k * ENC + (j - DEC)];
        else                      v = Whh[k * (4 * DEC) + (j - DEC - ENC)];
        g_Whcat[i] = v;
    }
    for (int i = idx; i < ENC * 1024; i += stride) {
        int k = i >> 10, j = i & 1023;
        g_Winit[i] = (j < DEC) ? Winith[k * DEC + j] : Winitc[k * DEC + (j - DEC)];
    }
    for (int i = idx; i < DEC * VOC; i += stride)
        g_Wfc_h[i] = __float2half_rn(Wfc[i]);
    for (int i = idx; i < BATCH * PIX * ENC; i += stride)
        g_enc_h[i] = __float2half_rn(enc[i]);
    if (idx < TSTEPS * BATCH) {
        int t = idx / BATCH, b = idx - t * BATCH;
        g_mask[idx] = (t < cap_len[b] - 1) ? 1.f : 0.f;
    }
    if (idx < BATCH * MAXLEN) out[CAP_OFF + idx] = (float)captions[idx];
    if (idx < BATCH)          out[LEN_OFF + idx] = (float)(cap_len[idx] - 1);
}

// ---------------- mean over pixels ----------------
__global__ void mean_kernel(const float* __restrict__ enc)
{
    int b = blockIdx.y;
    int d = blockIdx.x * 256 + threadIdx.x;
    const float* ep = enc + (size_t)b * PIX * ENC + d;
    float s = 0.f;
    for (int p = 0; p < PIX; p++) s += ep[(size_t)p * ENC];
    g_mean[b * ENC + d] = s * (1.f / (float)PIX);
}

// ---------------- reduce init partials -> h0 (buf 1), c0 ----------------
__global__ void ireduce_kernel(const float* __restrict__ b_init_h,
                               const float* __restrict__ b_init_c)
{
    int idx = blockIdx.x * 256 + threadIdx.x;
    int b = idx >> 10, col = idx & 1023;
    float v = 0.f;
#pragma unroll
    for (int z = 0; z < ISPLIT; z++) v += g_ipart[(size_t)(z * BATCH + b) * 1024 + col];
    if (col < DEC) g_hbuf[1][b * DEC + col] = v + b_init_h[col];
    else           g_c[b * DEC + (col - DEC)] = v + b_init_c[col - DEC];
}

// ---------------- fused attention scores + softmax (reduces hproj partials) --------
__global__ void att_softmax_kernel(const float* __restrict__ att_enc,
                                   const float* __restrict__ hpart,
                                   const float* __restrict__ b_dec_att,
                                   const float* __restrict__ Wf,
                                   const float* __restrict__ bf,
                                   const int* __restrict__ cap_len, int t,
                                   float* __restrict__ alpha,
                                   float* __restrict__ alphas_out)
{
    __shared__ float sdec[ATT];
    __shared__ float swf[ATT];
    __shared__ float se[256];
    __shared__ float red[256];
    const int b = blockIdx.x, tid = threadIdx.x;

    for (int k = tid; k < ATT; k += 256) {
        float s = b_dec_att[k];
#pragma unroll
        for (int z = 0; z < HSPLIT; z++) s += hpart[(size_t)(z * BATCH + b) * HCAT + k];
        sdec[k] = s;
        swf[k] = Wf[k];
    }
    se[tid] = -1e30f;
    __syncthreads();

    const int warp = tid >> 5, lane = tid & 31;
    const float bf0 = bf[0];
    for (int p = warp; p < PIX; p += 8) {
        const float* ae = att_enc + ((size_t)(b * PIX + p)) * ATT;
        float acc = 0.f;
        for (int k = lane; k < ATT; k += 32)
            acc += tanh_fast(ae[k] + sdec[k]) * swf[k];
#pragma unroll
        for (int o = 16; o; o >>= 1) acc += __shfl_down_sync(0xffffffffu, acc, o);
        if (lane == 0) se[p] = acc + bf0;
    }
    __syncthreads();

    red[tid] = se[tid]; __syncthreads();
    for (int s = 128; s; s >>= 1) { if (tid < s) red[tid] = fmaxf(red[tid], red[tid + s]); __syncthreads(); }
    float mx = red[0]; __syncthreads();
    float ex = (tid < PIX) ? __expf(se[tid] - mx) : 0.f;
    red[tid] = ex; __syncthreads();
    for (int s = 128; s; s >>= 1) { if (tid < s) red[tid] += red[tid + s]; __syncthreads(); }
    float inv = 1.f / red[0];
    if (tid < PIX) {
        float a = ex * inv;
        alpha[b * PIX + tid] = a;
        float m = (t < cap_len[b] - 1) ? 1.f : 0.f;
        alphas_out[(size_t)b * TSTEPS * PIX + (size_t)t * PIX + tid] = a * m;
    }
}

// ---------------- awe = sigmoid(fbeta_proj) * (alpha @ enc_fp16); x = [emb_t | awe] -
__global__ void awe_x_kernel(const float* __restrict__ alpha,
                             const float* __restrict__ hpart, const float* __restrict__ b_fbeta,
                             const float* __restrict__ emb, const int* __restrict__ captions,
                             int t, float* __restrict__ x)
{
    const int b = blockIdx.y, chunk = blockIdx.x, tid = threadIdx.x;
    if (chunk == 2) {
        if (tid < 128) {
            int tok = captions[b * MAXLEN + t];
            *(float4*)&x[b * XDIM + tid * 4] = *(const float4*)&emb[(size_t)tok * EMBD + tid * 4];
        }
        return;
    }
    __shared__ float sa[PIX];
    if (tid < PIX) sa[tid] = alpha[b * PIX + tid];
    __syncthreads();
    const int d = chunk * 1024 + tid * 4;
    float4 acc = make_float4(0,0,0,0);
    const __half* ep = g_enc_h + (size_t)b * PIX * ENC + d;
#pragma unroll 4
    for (int p = 0; p < PIX; p++) {
        float a = sa[p];
        uint2 r = *(const uint2*)(ep + (size_t)p * ENC);
        __half2 h0 = *(const __half2*)&r.x;
        __half2 h1 = *(const __half2*)&r.y;
        acc.x = fmaf(a, __low2float(h0),  acc.x);
        acc.y = fmaf(a, __high2float(h0), acc.y);
        acc.z = fmaf(a, __low2float(h1),  acc.z);
        acc.w = fmaf(a, __high2float(h1), acc.w);
    }
    // gate = sigmoid(hproj fbeta segment + b_fbeta)
    float4 g = make_float4(b_fbeta[d], b_fbeta[d+1], b_fbeta[d+2], b_fbeta[d+3]);
#pragma unroll
    for (int z = 0; z < HSPLIT; z++) {
        float4 p4 = *(const float4*)&hpart[(size_t)(z * BATCH + b) * HCAT + DEC + d];
        g.x += p4.x; g.y += p4.y; g.z += p4.z; g.w += p4.w;
    }
    g.x = sigmoidf_(g.x); g.y = sigmoidf_(g.y); g.z = sigmoidf_(g.z); g.w = sigmoidf_(g.w);
    *(float4*)&x[b * XDIM + EMBD + d] =
        make_float4(acc.x * g.x, acc.y * g.y, acc.z * g.z, acc.w * g.w);
}

// ---------------- LSTM update (reduces gates partials + hh segment + biases) --------
__global__ void lstm_kernel(const float* __restrict__ gpart, const float* __restrict__ hpart,
                            const float* __restrict__ b_ih, const float* __restrict__ b_hh,
                            const int* __restrict__ cap_len, int t,
                            const float* __restrict__ hprev, float* __restrict__ hnew)
{
    const int b = blockIdx.x, j = threadIdx.x;
    float gv[4];
#pragma unroll
    for (int s = 0; s < 4; s++) {
        const int col = s * DEC + j;
        float v = b_ih[col] + b_hh[col];
#pragma unroll
        for (int z = 0; z < GSPLIT; z++) v += gpart[(size_t)(z * BATCH + b) * (4 * DEC) + col];
#pragma unroll
        for (int z = 0; z < HSPLIT; z++) v += hpart[(size_t)(z * BATCH + b) * HCAT + (DEC + ENC) + col];
        gv[s] = v;
    }
    const float hp = hprev[b * DEC + j];
    if (t < cap_len[b] - 1) {
        float c_old = g_c[b * DEC + j];
        float cn = sigmoidf_(gv[1]) * c_old + sigmoidf_(gv[0]) * tanhf(gv[2]);
        g_c[b * DEC + j] = cn;
        hnew[b * DEC + j] = sigmoidf_(gv[3]) * tanhf(cn);
    } else {
        hnew[b * DEC + j] = hp;
    }
}

// ---------------- host launcher ----------------
extern "C" void kernel_launch(void* const* d_in, const int* in_sizes, int n_in,
                              void* d_out, int out_size)
{
    const float* enc        = (const float*)d_in[0];
    const int*   captions   = (const int*)  d_in[1];
    const int*   cap_len    = (const int*)  d_in[2];
    const float* emb        = (const float*)d_in[3];
    const float* W_enc_att  = (const float*)d_in[4];
    const float* b_enc_att  = (const float*)d_in[5];
    const float* W_dec_att  = (const float*)d_in[6];
    const float* b_dec_att  = (const float*)d_in[7];
    const float* W_full_att = (const float*)d_in[8];
    const float* b_full_att = (const float*)d_in[9];
    const float* W_init_h   = (const float*)d_in[10];
    const float* b_init_h   = (const float*)d_in[11];
    const float* W_init_c   = (const float*)d_in[12];
    const float* b_init_c   = (const float*)d_in[13];
    const float* b_fbeta    = (const float*)d_in[15];
    const float* W_ih       = (const float*)d_in[16];
    const float* b_ih       = (const float*)d_in[18];
    const float* b_hh       = (const float*)d_in[19];
    const float* W_fc       = (const float*)d_in[20];
    const float* b_fc       = (const float*)d_in[21];
    const float* Wfbeta     = (const float*)d_in[14];
    float* out = (float*)d_out;
    (void)in_sizes; (void)n_in; (void)out_size;

    float *pWhcat, *pWinit, *pmask, *pmean, *phb0, *phb1, *patt, *php, *pgp, *pip, *palpha, *px;
    __half *pWfc_h;
    cudaGetSymbolAddress((void**)&pWhcat, g_Whcat);
    cudaGetSymbolAddress((void**)&pWinit, g_Winit);
    cudaGetSymbolAddress((void**)&pmask,  g_mask);
    cudaGetSymbolAddress((void**)&pmean,  g_mean);
    cudaGetSymbolAddress((void**)&phb0,   g_hbuf);
    phb1 = phb0 + BATCH * DEC;
    cudaGetSymbolAddress((void**)&patt,   g_att_enc);
    cudaGetSymbolAddress((void**)&php,    g_hpart);
    cudaGetSymbolAddress((void**)&pgp,    g_gpart);
    cudaGetSymbolAddress((void**)&pip,    g_ipart);
    cudaGetSymbolAddress((void**)&palpha, g_alpha);
    cudaGetSymbolAddress((void**)&px,     g_x);
    cudaGetSymbolAddress((void**)&pWfc_h, g_Wfc_h);
    float* hbuf[2] = {phb0, phb1};

    static cudaStream_t s2 = nullptr;
    static cudaEvent_t evH = nullptr, evP0 = nullptr, evP1 = nullptr;
    if (!s2) {
        cudaStreamCreateWithFlags(&s2, cudaStreamNonBlocking);
        cudaEventCreateWithFlags(&evH,  cudaEventDisableTiming);
        cudaEventCreateWithFlags(&evP0, cudaEventDisableTiming);
        cudaEventCreateWithFlags(&evP1, cudaEventDisableTiming);
    }
    cudaEvent_t evP[2] = {evP0, evP1};

    // ---- prologue ----
    init_kernel<<<4096, 256>>>(W_dec_att, Wfbeta, W_ih /*unused pattern*/ == nullptr ? W_ih : (const float*)d_in[17],
                               W_init_h, W_init_c, W_fc, enc, captions, cap_len, out);
    mean_kernel<<<dim3(ENC / 256, BATCH), 256>>>(enc);
    gemm_k<<<dim3(8, 1, ISPLIT), 256>>>(pmean, ENC, pWinit, 1024, pip, 1024,
                                        1024, ENC / ISPLIT, (const float*)nullptr, (const float*)nullptr);
    ireduce_kernel<<<(BATCH * 1024) / 256, 256>>>(b_init_h, b_init_c);
    gemm_k<<<dim3(ATT / 128, (BATCH * PIX) / 64, 1), 256>>>(enc, ENC, W_enc_att, ATT,
                                                            patt, ATT, ATT, ENC,
                                                            b_enc_att, (const float*)nullptr);

    // ---- decode loop ----
    for (int t = 0; t < TSTEPS; t++) {
        const float* hprev = hbuf[(t + 1) & 1];
        float* hnew = hbuf[t & 1];

        // hproj partials: h_prev @ Whcat (64 x 4608), split-K 8
        gemm_k<<<dim3(HCAT / 128, 1, HSPLIT), 256>>>(hprev, DEC, pWhcat, HCAT, php, HCAT,
                                                     HCAT, DEC / HSPLIT,
                                                     (const float*)nullptr, (const float*)nullptr);
        att_softmax_kernel<<<BATCH, 256>>>(patt, php, b_dec_att, W_full_att, b_full_att,
                                           cap_len, t, palpha, out + ALPHA_OFF);
        awe_x_kernel<<<dim3(3, BATCH), 256>>>(palpha, php, b_fbeta, emb, captions, t, px);
        // gates partials: x @ W_ih (64 x 2048), split-K 16 (K=2560)
        gemm_k<<<dim3((4 * DEC) / 128, 1, GSPLIT), 256>>>(px, XDIM, W_ih, 4 * DEC, pgp, 4 * DEC,
                                                          4 * DEC, XDIM / GSPLIT,
                                                          (const float*)nullptr, (const float*)nullptr);
        if (t >= 2) cudaStreamWaitEvent(0, evP[t & 1], 0);
        lstm_kernel<<<BATCH, DEC>>>(pgp, php, b_ih, b_hh, cap_len, t, hprev, hnew);

        // preds on side stream: (h_t @ W_fc_fp16 + b_fc) * mask
        cudaEventRecord(evH, 0);
        cudaStreamWaitEvent(s2, evH, 0);
        gemm_k<<<dim3((VOC + 127) / 128, 1, 1), 256, 0, s2>>>(
            hnew, DEC, pWfc_h, VOC,
            out + PRED_OFF + (size_t)t * VOC, TSTEPS * VOC,
            VOC, DEC, b_fc, pmask + t * BATCH);
        cudaEventRecord(evP[t & 1], s2);
    }
    cudaStreamWaitEvent(0, evP[0], 0);
    cudaStreamWaitEvent(0, evP[1], 0);
}

// round 5
// speedup vs baseline: 3.6829x; 1.0305x over previous
#include <cuda_runtime.h>
#include <cuda_fp16.h>
#include <math.h>
#include <stdint.h>

// Problem constants
#define BATCH   64
#define PIX     196
#define ENC     2048
#define DEC     512
#define ATT     512
#define EMBD    512
#define VOC     10000
#define MAXLEN  52
#define TSTEPS  51
#define HCAT    4608     // 512 dec_att | 2048 fbeta | 2048 hh
#define XDIM    2560     // EMBD + ENC

// Output layout (flattened tuple, float32)
#define PRED_OFF   0
#define CAP_OFF    32640000
#define LEN_OFF    32643328
#define ALPHA_OFF  32643392

#define HSPLIT 8
#define GSPLIT 16
#define ISPLIT 8

#define MTOT  (TSTEPS * BATCH)   // 3264 = 51 * 64
#define NPAD  10112              // 79*128 (>= VOC), zero-padded WfcT rows

// ---------------- scratch ----------------
__device__ float  g_Whcat[DEC * HCAT];
__device__ float  g_Winit[ENC * 1024];
__device__ __half g_enc_h[BATCH * PIX * ENC];
__device__ __half g_WfcT[NPAD * DEC];           // W_fc transposed [n][k], fp16, padded
__device__ __half g_h16[MTOT * DEC];            // h history (t*64+b rows), fp16
__device__ float  g_mask[TSTEPS * BATCH];
__device__ float  g_mean[BATCH * ENC];
__device__ float  g_h[BATCH * DEC];
__device__ float  g_c[BATCH * DEC];
__device__ float  g_att_enc[BATCH * PIX * ATT];
__device__ float  g_hpart[HSPLIT * BATCH * HCAT];
__device__ float  g_gpart[GSPLIT * BATCH * 4 * DEC];
__device__ float  g_ipart[ISPLIT * BATCH * 1024];
__device__ float  g_alpha[BATCH * PIX];
__device__ float  g_x[BATCH * XDIM];

__device__ __forceinline__ float sigmoidf_(float x) { return 1.f / (1.f + __expf(-x)); }
__device__ __forceinline__ float tanh_fast(float x) {
    float y; asm("tanh.approx.f32 %0, %1;" : "=f"(y) : "f"(x)); return y;
}

// ============ batched predictions via HMMA (mma.sync m16n8k16) =====================
// D[3264,10000] = h_all(fp16)[M,K=512] @ WfcT(fp16)[N,K]^T, +bias, *mask.
// grid (79, 51), 256 threads (8 warps). BM=64, BN=128, BK=32.
// Warp layout 2(m) x 4(n), warp tile 32x32 = 2x4 mma tiles of m16n8.
#define SA_STRIDE 40   // halfs; 80B row stride -> conflict-free fragment loads
#define SB_STRIDE 40

__global__ void __launch_bounds__(256)
preds_mma_kernel(const float* __restrict__ b_fc, const float* __restrict__ mask,
                 float* __restrict__ out)
{
    __shared__ __half sA[64][SA_STRIDE];
    __shared__ __half sB[128][SB_STRIDE];

    const int tid  = threadIdx.x;
    const int wid  = tid >> 5;
    const int lane = tid & 31;
    const int grp  = lane >> 2;       // 0..7
    const int tg   = lane & 3;        // 0..3
    const int wm   = wid >> 2;        // 0..1
    const int wn   = wid & 3;         // 0..3

    const int m0 = blockIdx.y * 64;
    const int n0 = blockIdx.x * 128;

    // global load coords: A one uint4/thread, B two uint4/thread
    const int arow = tid >> 2;            // 0..63
    const int aseg = (tid & 3) * 8;       // halfs
    const int brow = tid >> 2;            // 0..63 (two rows: brow, brow+64)
    const int bseg = (tid & 3) * 8;

    const __half* Ag = g_h16  + (size_t)(m0 + arow) * DEC + aseg;
    const __half* Bg = g_WfcT + (size_t)(n0 + brow) * DEC + bseg;

    float c[2][4][4];
#pragma unroll
    for (int i = 0; i < 2; i++)
#pragma unroll
        for (int j = 0; j < 4; j++)
#pragma unroll
            for (int q = 0; q < 4; q++) c[i][j][q] = 0.f;

    for (int kt = 0; kt < DEC / 32; kt++) {
        const int kb = kt * 32;
        __syncthreads();
        *(uint4*)&sA[arow][aseg]      = *(const uint4*)(Ag + kb);
        *(uint4*)&sB[brow][bseg]      = *(const uint4*)(Bg + kb);
        *(uint4*)&sB[brow + 64][bseg] = *(const uint4*)(Bg + (size_t)64 * DEC + kb);
        __syncthreads();

#pragma unroll
        for (int ks = 0; ks < 2; ks++) {
            const int k0 = ks * 16;
            uint32_t a[2][4];
#pragma unroll
            for (int mi = 0; mi < 2; mi++) {
                const int r = wm * 32 + mi * 16 + grp;
                a[mi][0] = *(const uint32_t*)&sA[r    ][k0 + tg * 2];
                a[mi][1] = *(const uint32_t*)&sA[r + 8][k0 + tg * 2];
                a[mi][2] = *(const uint32_t*)&sA[r    ][k0 + tg * 2 + 8];
                a[mi][3] = *(const uint32_t*)&sA[r + 8][k0 + tg * 2 + 8];
            }
#pragma unroll
            for (int ni = 0; ni < 4; ni++) {
                const int nr = wn * 32 + ni * 8 + grp;
                uint32_t b0 = *(const uint32_t*)&sB[nr][k0 + tg * 2];
                uint32_t b1 = *(const uint32_t*)&sB[nr][k0 + tg * 2 + 8];
#pragma unroll
                for (int mi = 0; mi < 2; mi++) {
                    asm volatile(
                        "mma.sync.aligned.m16n8k16.row.col.f32.f16.f16.f32 "
                        "{%0,%1,%2,%3}, {%4,%5,%6,%7}, {%8,%9}, {%0,%1,%2,%3};"
                        : "+f"(c[mi][ni][0]), "+f"(c[mi][ni][1]),
                          "+f"(c[mi][ni][2]), "+f"(c[mi][ni][3])
                        : "r"(a[mi][0]), "r"(a[mi][1]), "r"(a[mi][2]), "r"(a[mi][3]),
                          "r"(b0), "r"(b1));
                }
            }
        }
    }

    // epilogue: (acc + bias) * mask -> out[b][t][n]
#pragma unroll
    for (int mi = 0; mi < 2; mi++) {
#pragma unroll
        for (int half = 0; half < 2; half++) {
            const int m = m0 + wm * 32 + mi * 16 + grp + half * 8;
            const int tt = m >> 6, bb = m & 63;
            const float ms = mask[tt * BATCH + bb];
            float* orow = out + PRED_OFF + ((size_t)bb * TSTEPS + tt) * VOC;
#pragma unroll
            for (int ni = 0; ni < 4; ni++) {
                const int n = n0 + wn * 32 + ni * 8 + tg * 2;
                if (n + 1 < VOC) {
                    orow[n]     = (c[mi][ni][half * 2]     + b_fc[n])     * ms;
                    orow[n + 1] = (c[mi][ni][half * 2 + 1] + b_fc[n + 1]) * ms;
                } else if (n < VOC) {
                    orow[n] = (c[mi][ni][half * 2] + b_fc[n]) * ms;
                }
            }
        }
    }
}

// ---------------- GEMM: BM=64, BN=128, BK=16, 256 thr, 8x4/thread, double-buffered --
__global__ void __launch_bounds__(256)
gemm_k(const float* __restrict__ A, int lda,
       const float* __restrict__ B, int ldb,
       float* __restrict__ C, int ldc,
       int N, int Kc,
       const float* __restrict__ bias)
{
    __shared__ float As[2][16][64];
    __shared__ float Bs[2][16][128];

    const int tid = threadIdx.x;
    const int m0 = blockIdx.y * 64;
    const int n0 = blockIdx.x * 128;
    const int koff = blockIdx.z * Kc;

    const int ty  = tid >> 5;
    const int tx  = tid & 31;
    const int ar  = tid >> 2;
    const int akc = (tid & 3) * 4;
    const int bkr = tid >> 4;
    const int bnc = (tid & 15) * 8;

    const float* Aptr = A + (size_t)(m0 + ar) * lda + koff + akc;
    const float* Bptr = B + (size_t)(koff + bkr) * ldb + n0 + bnc;
    const size_t bstep = (size_t)16 * ldb;
    const int nk = Kc >> 4;

    float4 aR, bR0, bR1;
    aR  = *(const float4*)Aptr;
    bR0 = *(const float4*)Bptr;
    bR1 = *(const float4*)(Bptr + 4);
    As[0][akc+0][ar] = aR.x; As[0][akc+1][ar] = aR.y;
    As[0][akc+2][ar] = aR.z; As[0][akc+3][ar] = aR.w;
    *(float4*)&Bs[0][bkr][bnc]   = bR0;
    *(float4*)&Bs[0][bkr][bnc+4] = bR1;
    __syncthreads();

    float acc[8][4];
#pragma unroll
    for (int i = 0; i < 8; i++)
#pragma unroll
        for (int j = 0; j < 4; j++) acc[i][j] = 0.f;

    for (int kt = 0; kt < nk; kt++) {
        const int cur = kt & 1, nxt = cur ^ 1;
        if (kt + 1 < nk) {
            aR = *(const float4*)(Aptr + (kt + 1) * 16);
            const float* bp = Bptr + (size_t)(kt + 1) * bstep;
            bR0 = *(const float4*)bp;
            bR1 = *(const float4*)(bp + 4);
        }
#pragma unroll
        for (int kk = 0; kk < 16; kk++) {
            float4 a0 = *(const float4*)&As[cur][kk][ty * 8];
            float4 a1 = *(const float4*)&As[cur][kk][ty * 8 + 4];
            float4 b  = *(const float4*)&Bs[cur][kk][tx * 4];
            float av[8] = {a0.x,a0.y,a0.z,a0.w,a1.x,a1.y,a1.z,a1.w};
            float bv[4] = {b.x,b.y,b.z,b.w};
#pragma unroll
            for (int i = 0; i < 8; i++)
#pragma unroll
                for (int j = 0; j < 4; j++)
                    acc[i][j] = fmaf(av[i], bv[j], acc[i][j]);
        }
        if (kt + 1 < nk) {
            As[nxt][akc+0][ar] = aR.x; As[nxt][akc+1][ar] = aR.y;
            As[nxt][akc+2][ar] = aR.z; As[nxt][akc+3][ar] = aR.w;
            *(float4*)&Bs[nxt][bkr][bnc]   = bR0;
            *(float4*)&Bs[nxt][bkr][bnc+4] = bR1;
            __syncthreads();
        }
    }

    const bool split = (gridDim.z > 1);
    float* Co = C + (split ? (size_t)blockIdx.z * 64 * ldc : 0);
#pragma unroll
    for (int i = 0; i < 8; i++) {
        const int gm = m0 + ty * 8 + i;
        float* crow = Co + (size_t)gm * ldc;
        const int gn = n0 + tx * 4;
        float4 v = make_float4(acc[i][0], acc[i][1], acc[i][2], acc[i][3]);
        if (!split && bias) {
            v.x += bias[gn]; v.y += bias[gn+1]; v.z += bias[gn+2]; v.w += bias[gn+3];
        }
        *(float4*)&crow[gn] = v;
    }
}

// ---------------- init: weight concats, fp16 conversions, WfcT, mask, int outputs ---
__global__ void init_kernel(const float* __restrict__ Wdec, const float* __restrict__ Wfbeta,
                            const float* __restrict__ Whh,
                            const float* __restrict__ Winith, const float* __restrict__ Winitc,
                            const float* __restrict__ Wfc, const float* __restrict__ enc,
                            const int* __restrict__ captions, const int* __restrict__ cap_len,
                            float* __restrict__ out)
{
    int idx = blockIdx.x * blockDim.x + threadIdx.x;
    int stride = gridDim.x * blockDim.x;
    for (int i = idx; i < DEC * HCAT; i += stride) {
        int k = i / HCAT, j = i - k * HCAT;
        float v;
        if (j < DEC)              v = Wdec[k * DEC + j];
        else if (j < DEC + ENC)   v = Wfbeta[k * ENC + (j - DEC)];
        else                      v = Whh[k * (4 * DEC) + (j - DEC - ENC)];
        g_Whcat[i] = v;
    }
    for (int i = idx; i < ENC * 1024; i += stride) {
        int k = i >> 10, j = i & 1023;
        g_Winit[i] = (j < DEC) ? Winith[k * DEC + j] : Winitc[k * DEC + (j - DEC)];
    }
    for (int i = idx; i < BATCH * PIX * ENC; i += stride)
        g_enc_h[i] = __float2half_rn(enc[i]);
    // WfcT[n][k] = Wfc[k][n], fp16, zero-padded rows beyond VOC
    for (int i = idx; i < NPAD * DEC; i += stride) {
        int n = i >> 9, k = i & 511;
        g_WfcT[i] = (n < VOC) ? __float2half_rn(Wfc[(size_t)k * VOC + n]) : __ushort_as_half(0);
    }
    if (idx < TSTEPS * BATCH) {
        int t = idx / BATCH, b = idx - t * BATCH;
        g_mask[idx] = (t < cap_len[b] - 1) ? 1.f : 0.f;
    }
    if (idx < BATCH * MAXLEN) out[CAP_OFF + idx] = (float)captions[idx];
    if (idx < BATCH)          out[LEN_OFF + idx] = (float)(cap_len[idx] - 1);
}

// ---------------- mean over pixels ----------------
__global__ void mean_kernel(const float* __restrict__ enc)
{
    int b = blockIdx.y;
    int d = blockIdx.x * 256 + threadIdx.x;
    const float* ep = enc + (size_t)b * PIX * ENC + d;
    float s = 0.f;
    for (int p = 0; p < PIX; p++) s += ep[(size_t)p * ENC];
    g_mean[b * ENC + d] = s * (1.f / (float)PIX);
}

// ---------------- reduce init partials -> h0, c0 ----------------
__global__ void ireduce_kernel(const float* __restrict__ b_init_h,
                               const float* __restrict__ b_init_c)
{
    int idx = blockIdx.x * 256 + threadIdx.x;
    int b = idx >> 10, col = idx & 1023;
    float v = 0.f;
#pragma unroll
    for (int z = 0; z < ISPLIT; z++) v += g_ipart[(size_t)(z * BATCH + b) * 1024 + col];
    if (col < DEC) g_h[b * DEC + col] = v + b_init_h[col];
    else           g_c[b * DEC + (col - DEC)] = v + b_init_c[col - DEC];
}

// ---------------- fused attention scores + softmax ----------------
__global__ void att_softmax_kernel(const float* __restrict__ att_enc,
                                   const float* __restrict__ hpart,
                                   const float* __restrict__ b_dec_att,
                                   const float* __restrict__ Wf,
                                   const float* __restrict__ bf,
                                   const int* __restrict__ cap_len, int t,
                                   float* __restrict__ alpha,
                                   float* __restrict__ alphas_out)
{
    __shared__ float sdec[ATT];
    __shared__ float swf[ATT];
    __shared__ float se[256];
    __shared__ float red[256];
    const int b = blockIdx.x, tid = threadIdx.x;

    for (int k = tid; k < ATT; k += 256) {
        float s = b_dec_att[k];
#pragma unroll
        for (int z = 0; z < HSPLIT; z++) s += hpart[(size_t)(z * BATCH + b) * HCAT + k];
        sdec[k] = s;
        swf[k] = Wf[k];
    }
    se[tid] = -1e30f;
    __syncthreads();

    const int warp = tid >> 5, lane = tid & 31;
    const float bf0 = bf[0];
    for (int p = warp; p < PIX; p += 8) {
        const float* ae = att_enc + ((size_t)(b * PIX + p)) * ATT;
        float acc = 0.f;
        for (int k = lane; k < ATT; k += 32)
            acc += tanh_fast(ae[k] + sdec[k]) * swf[k];
#pragma unroll
        for (int o = 16; o; o >>= 1) acc += __shfl_down_sync(0xffffffffu, acc, o);
        if (lane == 0) se[p] = acc + bf0;
    }
    __syncthreads();

    red[tid] = se[tid]; __syncthreads();
    for (int s = 128; s; s >>= 1) { if (tid < s) red[tid] = fmaxf(red[tid], red[tid + s]); __syncthreads(); }
    float mx = red[0]; __syncthreads();
    float ex = (tid < PIX) ? __expf(se[tid] - mx) : 0.f;
    red[tid] = ex; __syncthreads();
    for (int s = 128; s; s >>= 1) { if (tid < s) red[tid] += red[tid + s]; __syncthreads(); }
    float inv = 1.f / red[0];
    if (tid < PIX) {
        float a = ex * inv;
        alpha[b * PIX + tid] = a;
        float m = (t < cap_len[b] - 1) ? 1.f : 0.f;
        alphas_out[(size_t)b * TSTEPS * PIX + (size_t)t * PIX + tid] = a * m;
    }
}

// ---------------- awe + x build ----------------
__global__ void awe_x_kernel(const float* __restrict__ alpha,
                             const float* __restrict__ hpart, const float* __restrict__ b_fbeta,
                             const float* __restrict__ emb, const int* __restrict__ captions,
                             int t, float* __restrict__ x)
{
    const int b = blockIdx.y, chunk = blockIdx.x, tid = threadIdx.x;
    if (chunk == 2) {
        if (tid < 128) {
            int tok = captions[b * MAXLEN + t];
            *(float4*)&x[b * XDIM + tid * 4] = *(const float4*)&emb[(size_t)tok * EMBD + tid * 4];
        }
        return;
    }
    __shared__ float sa[PIX];
    if (tid < PIX) sa[tid] = alpha[b * PIX + tid];
    __syncthreads();
    const int d = chunk * 1024 + tid * 4;
    float4 acc = make_float4(0,0,0,0);
    const __half* ep = g_enc_h + (size_t)b * PIX * ENC + d;
#pragma unroll 4
    for (int p = 0; p < PIX; p++) {
        float a = sa[p];
        uint2 r = *(const uint2*)(ep + (size_t)p * ENC);
        __half2 h0 = *(const __half2*)&r.x;
        __half2 h1 = *(const __half2*)&r.y;
        acc.x = fmaf(a, __low2float(h0),  acc.x);
        acc.y = fmaf(a, __high2float(h0), acc.y);
        acc.z = fmaf(a, __low2float(h1),  acc.z);
        acc.w = fmaf(a, __high2float(h1), acc.w);
    }
    float4 g = make_float4(b_fbeta[d], b_fbeta[d+1], b_fbeta[d+2], b_fbeta[d+3]);
#pragma unroll
    for (int z = 0; z < HSPLIT; z++) {
        float4 p4 = *(const float4*)&hpart[(size_t)(z * BATCH + b) * HCAT + DEC + d];
        g.x += p4.x; g.y += p4.y; g.z += p4.z; g.w += p4.w;
    }
    g.x = sigmoidf_(g.x); g.y = sigmoidf_(g.y); g.z = sigmoidf_(g.z); g.w = sigmoidf_(g.w);
    *(float4*)&x[b * XDIM + EMBD + d] =
        make_float4(acc.x * g.x, acc.y * g.y, acc.z * g.z, acc.w * g.w);
}

// ---------------- LSTM update + fp16 h history ----------------
__global__ void lstm_kernel(const float* __restrict__ gpart, const float* __restrict__ hpart,
                            const float* __restrict__ b_ih, const float* __restrict__ b_hh,
                            const int* __restrict__ cap_len, int t)
{
    const int b = blockIdx.x, j = threadIdx.x;
    float gv[4];
#pragma unroll
    for (int s = 0; s < 4; s++) {
        const int col = s * DEC + j;
        float v = b_ih[col] + b_hh[col];
#pragma unroll
        for (int z = 0; z < GSPLIT; z++) v += gpart[(size_t)(z * BATCH + b) * (4 * DEC) + col];
#pragma unroll
        for (int z = 0; z < HSPLIT; z++) v += hpart[(size_t)(z * BATCH + b) * HCAT + (DEC + ENC) + col];
        gv[s] = v;
    }
    float h = g_h[b * DEC + j];
    if (t < cap_len[b] - 1) {
        float c_old = g_c[b * DEC + j];
        float cn = sigmoidf_(gv[1]) * c_old + sigmoidf_(gv[0]) * tanhf(gv[2]);
        g_c[b * DEC + j] = cn;
        h = sigmoidf_(gv[3]) * tanhf(cn);
        g_h[b * DEC + j] = h;
    }
    g_h16[((size_t)t * BATCH + b) * DEC + j] = __float2half_rn(h);
}

// ---------------- host launcher ----------------
extern "C" void kernel_launch(void* const* d_in, const int* in_sizes, int n_in,
                              void* d_out, int out_size)
{
    const float* enc        = (const float*)d_in[0];
    const int*   captions   = (const int*)  d_in[1];
    const int*   cap_len    = (const int*)  d_in[2];
    const float* emb        = (const float*)d_in[3];
    const float* W_enc_att  = (const float*)d_in[4];
    const float* b_enc_att  = (const float*)d_in[5];
    const float* W_dec_att  = (const float*)d_in[6];
    const float* b_dec_att  = (const float*)d_in[7];
    const float* W_full_att = (const float*)d_in[8];
    const float* b_full_att = (const float*)d_in[9];
    const float* W_init_h   = (const float*)d_in[10];
    const float* b_init_h   = (const float*)d_in[11];
    const float* W_init_c   = (const float*)d_in[12];
    const float* b_init_c   = (const float*)d_in[13];
    const float* W_fbeta    = (const float*)d_in[14];
    const float* b_fbeta    = (const float*)d_in[15];
    const float* W_ih       = (const float*)d_in[16];
    const float* W_hh       = (const float*)d_in[17];
    const float* b_ih       = (const float*)d_in[18];
    const float* b_hh       = (const float*)d_in[19];
    const float* W_fc       = (const float*)d_in[20];
    const float* b_fc       = (const float*)d_in[21];
    float* out = (float*)d_out;
    (void)in_sizes; (void)n_in; (void)out_size;

    float *pWhcat, *pWinit, *pmask, *pmean, *patt, *php, *pgp, *pip, *palpha, *px, *ph;
    cudaGetSymbolAddress((void**)&pWhcat, g_Whcat);
    cudaGetSymbolAddress((void**)&pWinit, g_Winit);
    cudaGetSymbolAddress((void**)&pmask,  g_mask);
    cudaGetSymbolAddress((void**)&pmean,  g_mean);
    cudaGetSymbolAddress((void**)&patt,   g_att_enc);
    cudaGetSymbolAddress((void**)&php,    g_hpart);
    cudaGetSymbolAddress((void**)&pgp,    g_gpart);
    cudaGetSymbolAddress((void**)&pip,    g_ipart);
    cudaGetSymbolAddress((void**)&palpha, g_alpha);
    cudaGetSymbolAddress((void**)&px,     g_x);
    cudaGetSymbolAddress((void**)&ph,     g_h);

    // ---- prologue (exactly 5 launches so ncu -s 5 profiles the first hproj) ----
    init_kernel<<<4096, 256>>>(W_dec_att, W_fbeta, W_hh, W_init_h, W_init_c,
                               W_fc, enc, captions, cap_len, out);
    mean_kernel<<<dim3(ENC / 256, BATCH), 256>>>(enc);
    gemm_k<<<dim3(8, 1, ISPLIT), 256>>>(pmean, ENC, pWinit, 1024, pip, 1024,
                                        1024, ENC / ISPLIT, nullptr);
    ireduce_kernel<<<(BATCH * 1024) / 256, 256>>>(b_init_h, b_init_c);
    gemm_k<<<dim3(ATT / 128, (BATCH * PIX) / 64, 1), 256>>>(enc, ENC, W_enc_att, ATT,
                                                            patt, ATT, ATT, ENC, b_enc_att);

    // ---- decode loop (5 kernels per step, no preds on critical path) ----
    for (int t = 0; t < TSTEPS; t++) {
        gemm_k<<<dim3(HCAT / 128, 1, HSPLIT), 256>>>(ph, DEC, pWhcat, HCAT, php, HCAT,
                                                     HCAT, DEC / HSPLIT, nullptr);
        att_softmax_kernel<<<BATCH, 256>>>(patt, php, b_dec_att, W_full_att, b_full_att,
                                           cap_len, t, palpha, out + ALPHA_OFF);
        awe_x_kernel<<<dim3(3, BATCH), 256>>>(palpha, php, b_fbeta, emb, captions, t, px);
        gemm_k<<<dim3((4 * DEC) / 128, 1, GSPLIT), 256>>>(px, XDIM, W_ih, 4 * DEC, pgp, 4 * DEC,
                                                          4 * DEC, XDIM / GSPLIT, nullptr);
        lstm_kernel<<<BATCH, DEC>>>(pgp, php, b_ih, b_hh, cap_len, t);
    }

    // ---- all predictions in one HMMA GEMM ----
    preds_mma_kernel<<<dim3(NPAD / 128, MTOT / 64), 256>>>(b_fc, pmask, out);
}

// round 6
// speedup vs baseline: 4.2838x; 1.1632x over previous
#include <cuda_runtime.h>
#include <cuda_fp16.h>
#include <math.h>
#include <stdint.h>

// Problem constants
#define BATCH   64
#define PIX     196
#define ENC     2048
#define DEC     512
#define ATT     512
#define EMBD    512
#define VOC     10000
#define MAXLEN  52
#define TSTEPS  51
#define HCAT    4608     // 512 dec_att | 2048 fbeta | 2048 hh
#define XDIM    2560     // EMBD + ENC

// Output layout (flattened tuple, float32)
#define PRED_OFF   0
#define CAP_OFF    32640000
#define LEN_OFF    32643328
#define ALPHA_OFF  32643392

#define HSPLIT 4         // hproj split-K (144 blocks)
#define GSPLIT 8         // gates split-K (128 blocks)
#define ISPLIT 8

#define MTOT  (TSTEPS * BATCH)   // 3264
#define NPAD  10112              // 79*128 >= VOC

#define NBLK  148                // persistent grid: 1 block/SM, co-resident

// ---------------- scratch ----------------
__device__ float  g_Whcat[DEC * HCAT];
__device__ float  g_Winit[ENC * 1024];
__device__ __half g_enc_h[BATCH * PIX * ENC];
__device__ __half g_WfcT[NPAD * DEC];
__device__ __half g_h16[MTOT * DEC];
__device__ float  g_mask[TSTEPS * BATCH];
__device__ float  g_mean[BATCH * ENC];
__device__ float  g_h[BATCH * DEC];
__device__ float  g_c[BATCH * DEC];
__device__ float  g_att_enc[BATCH * PIX * ATT];
__device__ float  g_hpart[HSPLIT * BATCH * HCAT];
__device__ float  g_gpart[GSPLIT * BATCH * 4 * DEC];
__device__ float  g_ipart[ISPLIT * BATCH * 1024];
__device__ float  g_e[BATCH * PIX];
__device__ float  g_x[BATCH * XDIM];

// grid barrier state
__device__ unsigned g_barcnt = 0;
__device__ unsigned g_bargen = 0;

__device__ __forceinline__ float sigmoidf_(float x) { return 1.f / (1.f + __expf(-x)); }
__device__ __forceinline__ float tanh_fast(float x) {
    float y; asm("tanh.approx.f32 %0, %1;" : "=f"(y) : "f"(x)); return y;
}
__device__ __forceinline__ unsigned ld_acq(const unsigned* p) {
    unsigned v;
    asm volatile("ld.acquire.gpu.u32 %0, [%1];" : "=r"(v) : "l"(p) : "memory");
    return v;
}
// sense-reversing grid barrier; all NBLK blocks must be co-resident
__device__ __forceinline__ void gbar(unsigned& gen) {
    __syncthreads();
    if (threadIdx.x == 0) {
        __threadfence();
        unsigned arrived = atomicAdd(&g_barcnt, 1u);
        if (arrived == NBLK - 1) {
            g_barcnt = 0;
            __threadfence();
            atomicAdd(&g_bargen, 1u);   // release
        } else {
            while (ld_acq(&g_bargen) == gen) { __nanosleep(32); }
        }
    }
    gen++;
    __syncthreads();
}

// ---------------- 64x128 GEMM tile, K-chunk; raw store (device fn) ----------------
// C[m][n0+...] += A(64 x K)[koff..] * B[koff.., n0..]; M=64 full, N covered fully.
__device__ __forceinline__ void gemm_tile(
    const float* __restrict__ A, int lda,
    const float* __restrict__ B, int ldb,
    float* __restrict__ C, int ldc,
    int n0, int koff, int nk,
    float* As, float* Bs, int tid)
{
    const int ty  = tid >> 5;
    const int tx  = tid & 31;
    const int ar  = tid >> 2;
    const int akc = (tid & 3) * 4;
    const int bkr = tid >> 4;
    const int bnc = (tid & 15) * 8;

    const float* Aptr = A + (size_t)ar * lda + koff + akc;
    const float* Bptr = B + (size_t)(koff + bkr) * ldb + n0 + bnc;
    const size_t bstep = (size_t)16 * ldb;

    float4 aR  = *(const float4*)Aptr;
    float4 bR0 = *(const float4*)Bptr;
    float4 bR1 = *(const float4*)(Bptr + 4);
    As[(akc+0)*64+ar] = aR.x; As[(akc+1)*64+ar] = aR.y;
    As[(akc+2)*64+ar] = aR.z; As[(akc+3)*64+ar] = aR.w;
    *(float4*)&Bs[bkr*128+bnc]   = bR0;
    *(float4*)&Bs[bkr*128+bnc+4] = bR1;
    __syncthreads();

    float acc[8][4];
#pragma unroll
    for (int i = 0; i < 8; i++)
#pragma unroll
        for (int j = 0; j < 4; j++) acc[i][j] = 0.f;

    for (int kt = 0; kt < nk; kt++) {
        const int cur = kt & 1, nxt = cur ^ 1;
        float* Ac = As + cur * 1024;
        float* Bc = Bs + cur * 2048;
        if (kt + 1 < nk) {
            aR = *(const float4*)(Aptr + (kt + 1) * 16);
            const float* bp = Bptr + (size_t)(kt + 1) * bstep;
            bR0 = *(const float4*)bp;
            bR1 = *(const float4*)(bp + 4);
        }
#pragma unroll
        for (int kk = 0; kk < 16; kk++) {
            float4 a0 = *(const float4*)&Ac[kk*64 + ty*8];
            float4 a1 = *(const float4*)&Ac[kk*64 + ty*8 + 4];
            float4 b  = *(const float4*)&Bc[kk*128 + tx*4];
            float av[8] = {a0.x,a0.y,a0.z,a0.w,a1.x,a1.y,a1.z,a1.w};
            float bv[4] = {b.x,b.y,b.z,b.w};
#pragma unroll
            for (int i = 0; i < 8; i++)
#pragma unroll
                for (int j = 0; j < 4; j++)
                    acc[i][j] = fmaf(av[i], bv[j], acc[i][j]);
        }
        if (kt + 1 < nk) {
            float* An = As + nxt * 1024;
            float* Bn = Bs + nxt * 2048;
            An[(akc+0)*64+ar] = aR.x; An[(akc+1)*64+ar] = aR.y;
            An[(akc+2)*64+ar] = aR.z; An[(akc+3)*64+ar] = aR.w;
            *(float4*)&Bn[bkr*128+bnc]   = bR0;
            *(float4*)&Bn[bkr*128+bnc+4] = bR1;
            __syncthreads();
        }
    }
#pragma unroll
    for (int i = 0; i < 8; i++) {
        float* crow = C + (size_t)(ty*8 + i) * ldc + n0 + tx*4;
        *(float4*)crow = make_float4(acc[i][0], acc[i][1], acc[i][2], acc[i][3]);
    }
}

// ============ persistent decode-loop kernel (all 51 steps, 5 phases/step) ============
__global__ void __launch_bounds__(256, 1)
decode_loop_kernel(const float* __restrict__ b_dec_att, const float* __restrict__ Wf,
                   const float* __restrict__ bf, const float* __restrict__ b_fbeta,
                   const float* __restrict__ emb, const int* __restrict__ captions,
                   const int* __restrict__ cap_len,
                   const float* __restrict__ W_ih,
                   const float* __restrict__ b_ih, const float* __restrict__ b_hh,
                   float* __restrict__ out)
{
    __shared__ float sA[2 * 16 * 64];     // 8KB  (gemm A, double buffered)
    __shared__ float sB[2 * 16 * 128];    // 16KB (gemm B)
    __shared__ float sdec[ATT];
    __shared__ float swf[ATT];
    __shared__ float sred[256];
    __shared__ float salpha[256];

    const int bid = blockIdx.x;
    const int tid = threadIdx.x;
    unsigned gen = ld_acq(&g_bargen);

    for (int t = 0; t < TSTEPS; t++) {
        // ---- phase 1: hproj partials (144 blocks) + emb->x copy (4 blocks) ----
        if (bid < 144) {
            const int nt = bid >> 2;      // 0..35
            const int z  = bid & 3;       // 0..3
            gemm_tile(g_h, DEC, g_Whcat, HCAT,
                      g_hpart + (size_t)z * 64 * HCAT, HCAT,
                      nt * 128, z * 128, 8, sA, sB, tid);
        } else {
            for (int b = bid - 144; b < BATCH; b += 4) {
                const int tok = captions[b * MAXLEN + t];
                if (tid < 128)
                    *(float4*)&g_x[b * XDIM + tid * 4] =
                        *(const float4*)&emb[(size_t)tok * EMBD + tid * 4];
            }
        }
        gbar(gen);

        // ---- phase 2: attention scores e[b,p] (128 blocks) ----
        if (bid < 128) {
            const int b = bid >> 1, ph = bid & 1;
            for (int k = tid; k < ATT; k += 256) {
                float s = b_dec_att[k];
#pragma unroll
                for (int z = 0; z < HSPLIT; z++)
                    s += g_hpart[(size_t)(z * BATCH + b) * HCAT + k];
                sdec[k] = s;
                swf[k] = Wf[k];
            }
            __syncthreads();
            const int warp = tid >> 5, lane = tid & 31;
            const float bf0 = bf[0];
            const int pbase = ph * 98;
            for (int p = pbase + warp; p < pbase + 98; p += 8) {
                const float* ae = g_att_enc + ((size_t)(b * PIX + p)) * ATT;
                float acc = 0.f;
                for (int k = lane; k < ATT; k += 32)
                    acc += tanh_fast(ae[k] + sdec[k]) * swf[k];
#pragma unroll
                for (int o = 16; o; o >>= 1) acc += __shfl_down_sync(0xffffffffu, acc, o);
                if (lane == 0) g_e[b * PIX + p] = acc + bf0;
            }
        }
        gbar(gen);

        // ---- phase 3: softmax + awe + x build + alphas out (128 blocks) ----
        if (bid < 128) {
            const int b = bid >> 1, chunk = bid & 1;
            float v = (tid < PIX) ? g_e[b * PIX + tid] : -1e30f;
            sred[tid] = v; __syncthreads();
            for (int s = 128; s; s >>= 1) { if (tid < s) sred[tid] = fmaxf(sred[tid], sred[tid+s]); __syncthreads(); }
            const float mx = sred[0]; __syncthreads();
            const float ex = (tid < PIX) ? __expf(v - mx) : 0.f;
            sred[tid] = ex; __syncthreads();
            for (int s = 128; s; s >>= 1) { if (tid < s) sred[tid] += sred[tid+s]; __syncthreads(); }
            const float inv = 1.f / sred[0];
            const float a = ex * inv;
            salpha[tid] = a;
            if (chunk == 0 && tid < PIX) {
                const float m = (t < cap_len[b] - 1) ? 1.f : 0.f;
                out[ALPHA_OFF + (size_t)b * TSTEPS * PIX + (size_t)t * PIX + tid] = a * m;
            }
            __syncthreads();

            const int d = chunk * 1024 + tid * 4;
            float4 acc = make_float4(0,0,0,0);
            const __half* ep = g_enc_h + (size_t)b * PIX * ENC + d;
#pragma unroll 4
            for (int p = 0; p < PIX; p++) {
                const float al = salpha[p];
                uint2 r = *(const uint2*)(ep + (size_t)p * ENC);
                __half2 h0 = *(const __half2*)&r.x;
                __half2 h1 = *(const __half2*)&r.y;
                acc.x = fmaf(al, __low2float(h0),  acc.x);
                acc.y = fmaf(al, __high2float(h0), acc.y);
                acc.z = fmaf(al, __low2float(h1),  acc.z);
                acc.w = fmaf(al, __high2float(h1), acc.w);
            }
            float4 g = make_float4(b_fbeta[d], b_fbeta[d+1], b_fbeta[d+2], b_fbeta[d+3]);
#pragma unroll
            for (int z = 0; z < HSPLIT; z++) {
                float4 p4 = *(const float4*)&g_hpart[(size_t)(z * BATCH + b) * HCAT + DEC + d];
                g.x += p4.x; g.y += p4.y; g.z += p4.z; g.w += p4.w;
            }
            g.x = sigmoidf_(g.x); g.y = sigmoidf_(g.y); g.z = sigmoidf_(g.z); g.w = sigmoidf_(g.w);
            *(float4*)&g_x[b * XDIM + EMBD + d] =
                make_float4(acc.x * g.x, acc.y * g.y, acc.z * g.z, acc.w * g.w);
        }
        gbar(gen);

        // ---- phase 4: gates partials (128 blocks, split-K 8, Kc=320) ----
        if (bid < 128) {
            const int nt = bid & 15;      // 0..15
            const int z  = bid >> 4;      // 0..7
            gemm_tile(g_x, XDIM, W_ih, 4 * DEC,
                      g_gpart + (size_t)z * 64 * (4 * DEC), 4 * DEC,
                      nt * 128, z * 320, 20, sA, sB, tid);
        }
        gbar(gen);

        // ---- phase 5: LSTM update + fp16 h history (64 blocks) ----
        if (bid < 64) {
            const int b = bid;
#pragma unroll
            for (int jj = 0; jj < 2; jj++) {
                const int j = tid + jj * 256;
                float gv[4];
#pragma unroll
                for (int s = 0; s < 4; s++) {
                    const int col = s * DEC + j;
                    float v = b_ih[col] + b_hh[col];
#pragma unroll
                    for (int z = 0; z < GSPLIT; z++)
                        v += g_gpart[(size_t)(z * BATCH + b) * (4 * DEC) + col];
#pragma unroll
                    for (int z = 0; z < HSPLIT; z++)
                        v += g_hpart[(size_t)(z * BATCH + b) * HCAT + (DEC + ENC) + col];
                    gv[s] = v;
                }
                float h = g_h[b * DEC + j];
                if (t < cap_len[b] - 1) {
                    const float c_old = g_c[b * DEC + j];
                    const float cn = sigmoidf_(gv[1]) * c_old + sigmoidf_(gv[0]) * tanhf(gv[2]);
                    g_c[b * DEC + j] = cn;
                    h = sigmoidf_(gv[3]) * tanhf(cn);
                    g_h[b * DEC + j] = h;
                }
                g_h16[((size_t)t * BATCH + b) * DEC + j] = __float2half_rn(h);
            }
        }
        gbar(gen);
    }
}

// ============ batched predictions via HMMA (unchanged from round 5) ================
#define SA_STRIDE 40
#define SB_STRIDE 40

__global__ void __launch_bounds__(256)
preds_mma_kernel(const float* __restrict__ b_fc, const float* __restrict__ mask,
                 float* __restrict__ out)
{
    __shared__ __half sAh[64][SA_STRIDE];
    __shared__ __half sBh[128][SB_STRIDE];

    const int tid  = threadIdx.x;
    const int wid  = tid >> 5;
    const int lane = tid & 31;
    const int grp  = lane >> 2;
    const int tg   = lane & 3;
    const int wm   = wid >> 2;
    const int wn   = wid & 3;

    const int m0 = blockIdx.y * 64;
    const int n0 = blockIdx.x * 128;

    const int arow = tid >> 2;
    const int aseg = (tid & 3) * 8;
    const int brow = tid >> 2;
    const int bseg = (tid & 3) * 8;

    const __half* Ag = g_h16  + (size_t)(m0 + arow) * DEC + aseg;
    const __half* Bg = g_WfcT + (size_t)(n0 + brow) * DEC + bseg;

    float c[2][4][4];
#pragma unroll
    for (int i = 0; i < 2; i++)
#pragma unroll
        for (int j = 0; j < 4; j++)
#pragma unroll
            for (int q = 0; q < 4; q++) c[i][j][q] = 0.f;

    for (int kt = 0; kt < DEC / 32; kt++) {
        const int kb = kt * 32;
        __syncthreads();
        *(uint4*)&sAh[arow][aseg]      = *(const uint4*)(Ag + kb);
        *(uint4*)&sBh[brow][bseg]      = *(const uint4*)(Bg + kb);
        *(uint4*)&sBh[brow + 64][bseg] = *(const uint4*)(Bg + (size_t)64 * DEC + kb);
        __syncthreads();

#pragma unroll
        for (int ks = 0; ks < 2; ks++) {
            const int k0 = ks * 16;
            uint32_t a[2][4];
#pragma unroll
            for (int mi = 0; mi < 2; mi++) {
                const int r = wm * 32 + mi * 16 + grp;
                a[mi][0] = *(const uint32_t*)&sAh[r    ][k0 + tg * 2];
                a[mi][1] = *(const uint32_t*)&sAh[r + 8][k0 + tg * 2];
                a[mi][2] = *(const uint32_t*)&sAh[r    ][k0 + tg * 2 + 8];
                a[mi][3] = *(const uint32_t*)&sAh[r + 8][k0 + tg * 2 + 8];
            }
#pragma unroll
            for (int ni = 0; ni < 4; ni++) {
                const int nr = wn * 32 + ni * 8 + grp;
                uint32_t b0 = *(const uint32_t*)&sBh[nr][k0 + tg * 2];
                uint32_t b1 = *(const uint32_t*)&sBh[nr][k0 + tg * 2 + 8];
#pragma unroll
                for (int mi = 0; mi < 2; mi++) {
                    asm volatile(
                        "mma.sync.aligned.m16n8k16.row.col.f32.f16.f16.f32 "
                        "{%0,%1,%2,%3}, {%4,%5,%6,%7}, {%8,%9}, {%0,%1,%2,%3};"
                        : "+f"(c[mi][ni][0]), "+f"(c[mi][ni][1]),
                          "+f"(c[mi][ni][2]), "+f"(c[mi][ni][3])
                        : "r"(a[mi][0]), "r"(a[mi][1]), "r"(a[mi][2]), "r"(a[mi][3]),
                          "r"(b0), "r"(b1));
                }
            }
        }
    }

#pragma unroll
    for (int mi = 0; mi < 2; mi++) {
#pragma unroll
        for (int half = 0; half < 2; half++) {
            const int m = m0 + wm * 32 + mi * 16 + grp + half * 8;
            const int tt = m >> 6, bb = m & 63;
            const float ms = mask[tt * BATCH + bb];
            float* orow = out + PRED_OFF + ((size_t)bb * TSTEPS + tt) * VOC;
#pragma unroll
            for (int ni = 0; ni < 4; ni++) {
                const int n = n0 + wn * 32 + ni * 8 + tg * 2;
                if (n + 1 < VOC) {
                    orow[n]     = (c[mi][ni][half * 2]     + b_fc[n])     * ms;
                    orow[n + 1] = (c[mi][ni][half * 2 + 1] + b_fc[n + 1]) * ms;
                } else if (n < VOC) {
                    orow[n] = (c[mi][ni][half * 2] + b_fc[n]) * ms;
                }
            }
        }
    }
}

// ---------------- prologue GEMM kernel (fp32, bias) ----------------
__global__ void __launch_bounds__(256)
gemm_k(const float* __restrict__ A, int lda,
       const float* __restrict__ B, int ldb,
       float* __restrict__ C, int ldc,
       int N, int Kc,
       const float* __restrict__ bias)
{
    __shared__ float As[2 * 16 * 64];
    __shared__ float Bs[2 * 16 * 128];
    const int tid = threadIdx.x;
    const int n0 = blockIdx.x * 128;
    const int koff = blockIdx.z * Kc;
    const float* Ab = A + (size_t)blockIdx.y * 64 * lda;
    const bool split = (gridDim.z > 1);
    float* Co = C + (size_t)blockIdx.y * 64 * ldc + (split ? (size_t)blockIdx.z * 64 * ldc * gridDim.y : 0);
    // NOTE: for split use, gridDim.y==1 in this code path (z-offset = z*64*ldc)
    if (split) Co = C + (size_t)blockIdx.z * 64 * ldc;

    gemm_tile(Ab, lda, B, ldb, Co, ldc, n0, koff, Kc >> 4, As, Bs, tid);

    if (!split && bias) {
        // add bias in-place for this tile
        __syncthreads();
        for (int i = tid; i < 64 * 128; i += 256) {
            const int r = i >> 7, cn = i & 127;
            Co[(size_t)r * ldc + n0 + cn] += bias[n0 + cn];
        }
    }
}

// ---------------- init ----------------
__global__ void init_kernel(const float* __restrict__ Wdec, const float* __restrict__ Wfbeta,
                            const float* __restrict__ Whh,
                            const float* __restrict__ Winith, const float* __restrict__ Winitc,
                            const float* __restrict__ Wfc, const float* __restrict__ enc,
                            const int* __restrict__ captions, const int* __restrict__ cap_len,
                            float* __restrict__ out)
{
    int idx = blockIdx.x * blockDim.x + threadIdx.x;
    int stride = gridDim.x * blockDim.x;
    for (int i = idx; i < DEC * HCAT; i += stride) {
        int k = i / HCAT, j = i - k * HCAT;
        float v;
        if (j < DEC)              v = Wdec[k * DEC + j];
        else if (j < DEC + ENC)   v = Wfbeta[k * ENC + (j - DEC)];
        else                      v = Whh[k * (4 * DEC) + (j - DEC - ENC)];
        g_Whcat[i] = v;
    }
    for (int i = idx; i < ENC * 1024; i += stride) {
        int k = i >> 10, j = i & 1023;
        g_Winit[i] = (j < DEC) ? Winith[k * DEC + j] : Winitc[k * DEC + (j - DEC)];
    }
    for (int i = idx; i < BATCH * PIX * ENC; i += stride)
        g_enc_h[i] = __float2half_rn(enc[i]);
    for (int i = idx; i < NPAD * DEC; i += stride) {
        int n = i >> 9, k = i & 511;
        g_WfcT[i] = (n < VOC) ? __float2half_rn(Wfc[(size_t)k * VOC + n]) : __ushort_as_half(0);
    }
    if (idx < TSTEPS * BATCH) {
        int t = idx / BATCH, b = idx - t * BATCH;
        g_mask[idx] = (t < cap_len[b] - 1) ? 1.f : 0.f;
    }
    if (idx < BATCH * MAXLEN) out[CAP_OFF + idx] = (float)captions[idx];
    if (idx < BATCH)          out[LEN_OFF + idx] = (float)(cap_len[idx] - 1);
}

__global__ void mean_kernel(const float* __restrict__ enc)
{
    int b = blockIdx.y;
    int d = blockIdx.x * 256 + threadIdx.x;
    const float* ep = enc + (size_t)b * PIX * ENC + d;
    float s = 0.f;
    for (int p = 0; p < PIX; p++) s += ep[(size_t)p * ENC];
    g_mean[b * ENC + d] = s * (1.f / (float)PIX);
}

__global__ void ireduce_kernel(const float* __restrict__ b_init_h,
                               const float* __restrict__ b_init_c)
{
    int idx = blockIdx.x * 256 + threadIdx.x;
    int b = idx >> 10, col = idx & 1023;
    float v = 0.f;
#pragma unroll
    for (int z = 0; z < ISPLIT; z++) v += g_ipart[(size_t)(z * BATCH + b) * 1024 + col];
    if (col < DEC) g_h[b * DEC + col] = v + b_init_h[col];
    else           g_c[b * DEC + (col - DEC)] = v + b_init_c[col - DEC];
}

// ---------------- host launcher ----------------
extern "C" void kernel_launch(void* const* d_in, const int* in_sizes, int n_in,
                              void* d_out, int out_size)
{
    const float* enc        = (const float*)d_in[0];
    const int*   captions   = (const int*)  d_in[1];
    const int*   cap_len    = (const int*)  d_in[2];
    const float* emb        = (const float*)d_in[3];
    const float* W_enc_att  = (const float*)d_in[4];
    const float* b_enc_att  = (const float*)d_in[5];
    const float* W_dec_att  = (const float*)d_in[6];
    const float* b_dec_att  = (const float*)d_in[7];
    const float* W_full_att = (const float*)d_in[8];
    const float* b_full_att = (const float*)d_in[9];
    const float* W_init_h   = (const float*)d_in[10];
    const float* b_init_h   = (const float*)d_in[11];
    const float* W_init_c   = (const float*)d_in[12];
    const float* b_init_c   = (const float*)d_in[13];
    const float* W_fbeta    = (const float*)d_in[14];
    const float* b_fbeta    = (const float*)d_in[15];
    const float* W_ih       = (const float*)d_in[16];
    const float* W_hh       = (const float*)d_in[17];
    const float* b_ih       = (const float*)d_in[18];
    const float* b_hh       = (const float*)d_in[19];
    const float* W_fc       = (const float*)d_in[20];
    const float* b_fc       = (const float*)d_in[21];
    float* out = (float*)d_out;
    (void)in_sizes; (void)n_in; (void)out_size;

    float *pWinit, *pmask, *pmean, *patt, *pip;
    cudaGetSymbolAddress((void**)&pWinit, g_Winit);
    cudaGetSymbolAddress((void**)&pmask,  g_mask);
    cudaGetSymbolAddress((void**)&pmean,  g_mean);
    cudaGetSymbolAddress((void**)&patt,   g_att_enc);
    cudaGetSymbolAddress((void**)&pip,    g_ipart);

    // ---- prologue ----
    init_kernel<<<4096, 256>>>(W_dec_att, W_fbeta, W_hh, W_init_h, W_init_c,
                               W_fc, enc, captions, cap_len, out);
    mean_kernel<<<dim3(ENC / 256, BATCH), 256>>>(enc);
    gemm_k<<<dim3(8, 1, ISPLIT), 256>>>(pmean, ENC, pWinit, 1024, pip, 1024,
                                        1024, ENC / ISPLIT, nullptr);
    ireduce_kernel<<<(BATCH * 1024) / 256, 256>>>(b_init_h, b_init_c);
    gemm_k<<<dim3(ATT / 128, (BATCH * PIX) / 64, 1), 256>>>(enc, ENC, W_enc_att, ATT,
                                                            patt, ATT, ATT, ENC, b_enc_att);

    // ---- entire decode loop: one persistent kernel ----
    decode_loop_kernel<<<NBLK, 256>>>(b_dec_att, W_full_att, b_full_att, b_fbeta,
                                      emb, captions, cap_len,
                                      W_ih, b_ih, b_hh, out);

    // ---- all predictions in one HMMA GEMM ----
    preds_mma_kernel<<<dim3(NPAD / 128, MTOT / 64), 256>>>(b_fc, pmask, out);
}

// round 7
// speedup vs baseline: 5.7499x; 1.3422x over previous
#include <cuda_runtime.h>
#include <cuda_fp16.h>
#include <math.h>
#include <stdint.h>

// Problem constants
#define BATCH   64
#define PIX     196
#define ENC     2048
#define DEC     512
#define ATT     512
#define EMBD    512
#define VOC     10000
#define MAXLEN  52
#define TSTEPS  51
#define HCAT    4608     // 512 dec_att | 2048 fbeta | 2048 hh
#define XDIM    2560     // EMBD + ENC

// Output layout (flattened tuple, float32)
#define PRED_OFF   0
#define CAP_OFF    32640000
#define LEN_OFF    32643328
#define ALPHA_OFF  32643392

#define HSPLIT 4         // hproj split-K
#define GSPLIT 8         // gates split-K
#define ISPLIT 8         // h0c0 split-K

#define MTOT  (TSTEPS * BATCH)   // 3264
#define NPAD  10112              // 79*128 >= VOC
#define NBLK  148                // persistent grid

// ---------------- scratch ----------------
__device__ __align__(16) __half g_WhcatT[HCAT * DEC];   // [n][k] fp16
__device__ __align__(16) __half g_WihT[4 * DEC * XDIM]; // [n][k] fp16
__device__ __align__(16) __half g_WencT[ATT * ENC];     // [n][k] fp16
__device__ __align__(16) __half g_WfcT[NPAD * DEC];     // [n][k] fp16
__device__ __align__(16) __half g_enc_h[BATCH * PIX * ENC];
__device__ __align__(16) __half g_h16cur[BATCH * DEC];  // current h, fp16
__device__ __align__(16) __half g_h16[MTOT * DEC];      // h history
__device__ __align__(16) __half g_x16[BATCH * XDIM];    // LSTM input x, fp16
__device__ float  g_Winit[ENC * 1024];
__device__ float  g_mask[TSTEPS * BATCH];
__device__ float  g_mean[BATCH * ENC];
__device__ float  g_c[BATCH * DEC];
__device__ float  g_att_enc[BATCH * PIX * ATT];
__device__ float  g_hpart[HSPLIT * BATCH * HCAT];
__device__ float  g_gpart[GSPLIT * BATCH * 4 * DEC];
__device__ float  g_ipart[ISPLIT * BATCH * 1024];
__device__ float  g_e[BATCH * PIX];

// grid barrier state
__device__ unsigned g_barcnt = 0;
__device__ unsigned g_bargen = 0;

__device__ __forceinline__ float sigmoidf_(float x) { return 1.f / (1.f + __expf(-x)); }
__device__ __forceinline__ float tanh_fast(float x) {
    float y; asm("tanh.approx.f32 %0, %1;" : "=f"(y) : "f"(x)); return y;
}
__device__ __forceinline__ unsigned ld_acq(const unsigned* p) {
    unsigned v;
    asm volatile("ld.acquire.gpu.u32 %0, [%1];" : "=r"(v) : "l"(p) : "memory");
    return v;
}
__device__ __forceinline__ void gbar(unsigned& gen) {
    __syncthreads();
    if (threadIdx.x == 0) {
        __threadfence();
        unsigned arrived = atomicAdd(&g_barcnt, 1u);
        if (arrived == NBLK - 1) {
            g_barcnt = 0;
            __threadfence();
            atomicAdd(&g_bargen, 1u);
        } else {
            while (ld_acq(&g_bargen) == gen) { __nanosleep(32); }
        }
    }
    gen++;
    __syncthreads();
}

// ---------------- HMMA 64x128 tile (fp16 in, fp32 acc), raw/biased store ----------
// C[0..63][n0..n0+127] (+=)? no: = A[64 x lda] rows x B[n][k] rows (n0..n0+127),
// K range [koff, koff + nsteps*32). sAh: 64*40 halfs, sBh: 128*40 halfs.
__device__ __forceinline__ void hmma_tile(
    const __half* __restrict__ Ag, int lda,
    const __half* __restrict__ Bg, int ldb,
    float* __restrict__ Cg, int ldc,
    int n0, int koff, int nsteps,
    const float* __restrict__ bias,
    __half* sAh, __half* sBh, int tid)
{
    const int wid  = tid >> 5;
    const int lane = tid & 31;
    const int grp  = lane >> 2;
    const int tg   = lane & 3;
    const int wm   = wid >> 2;
    const int wn   = wid & 3;

    const int arow = tid >> 2;            // 0..63
    const int aseg = (tid & 3) * 8;

    const __half* Ap = Ag + (size_t)arow * lda + koff + aseg;
    const __half* Bp = Bg + (size_t)(n0 + arow) * ldb + koff + aseg;

    float c[2][4][4];
#pragma unroll
    for (int i = 0; i < 2; i++)
#pragma unroll
        for (int j = 0; j < 4; j++)
#pragma unroll
            for (int q = 0; q < 4; q++) c[i][j][q] = 0.f;

    for (int kt = 0; kt < nsteps; kt++) {
        const int kb = kt * 32;
        __syncthreads();
        *(uint4*)&sAh[arow * 40 + aseg]        = *(const uint4*)(Ap + kb);
        *(uint4*)&sBh[arow * 40 + aseg]        = *(const uint4*)(Bp + kb);
        *(uint4*)&sBh[(arow + 64) * 40 + aseg] = *(const uint4*)(Bp + (size_t)64 * ldb + kb);
        __syncthreads();

#pragma unroll
        for (int ks = 0; ks < 2; ks++) {
            const int k0 = ks * 16;
            uint32_t a[2][4];
#pragma unroll
            for (int mi = 0; mi < 2; mi++) {
                const int r = wm * 32 + mi * 16 + grp;
                a[mi][0] = *(const uint32_t*)&sAh[(r    ) * 40 + k0 + tg * 2];
                a[mi][1] = *(const uint32_t*)&sAh[(r + 8) * 40 + k0 + tg * 2];
                a[mi][2] = *(const uint32_t*)&sAh[(r    ) * 40 + k0 + tg * 2 + 8];
                a[mi][3] = *(const uint32_t*)&sAh[(r + 8) * 40 + k0 + tg * 2 + 8];
            }
#pragma unroll
            for (int ni = 0; ni < 4; ni++) {
                const int nr = wn * 32 + ni * 8 + grp;
                uint32_t b0 = *(const uint32_t*)&sBh[nr * 40 + k0 + tg * 2];
                uint32_t b1 = *(const uint32_t*)&sBh[nr * 40 + k0 + tg * 2 + 8];
#pragma unroll
                for (int mi = 0; mi < 2; mi++) {
                    asm volatile(
                        "mma.sync.aligned.m16n8k16.row.col.f32.f16.f16.f32 "
                        "{%0,%1,%2,%3}, {%4,%5,%6,%7}, {%8,%9}, {%0,%1,%2,%3};"
                        : "+f"(c[mi][ni][0]), "+f"(c[mi][ni][1]),
                          "+f"(c[mi][ni][2]), "+f"(c[mi][ni][3])
                        : "r"(a[mi][0]), "r"(a[mi][1]), "r"(a[mi][2]), "r"(a[mi][3]),
                          "r"(b0), "r"(b1));
                }
            }
        }
    }

#pragma unroll
    for (int mi = 0; mi < 2; mi++) {
#pragma unroll
        for (int hh = 0; hh < 2; hh++) {
            const int row = wm * 32 + mi * 16 + grp + hh * 8;
            float* crow = Cg + (size_t)row * ldc;
#pragma unroll
            for (int ni = 0; ni < 4; ni++) {
                const int col = n0 + wn * 32 + ni * 8 + tg * 2;
                float v0 = c[mi][ni][hh * 2];
                float v1 = c[mi][ni][hh * 2 + 1];
                if (bias) { v0 += bias[col]; v1 += bias[col + 1]; }
                crow[col]     = v0;
                crow[col + 1] = v1;
            }
        }
    }
}

// ---------------- fp32 64x128 GEMM tile (prologue h0/c0 only) ----------------
__device__ __forceinline__ void gemm_tile(
    const float* __restrict__ A, int lda,
    const float* __restrict__ B, int ldb,
    float* __restrict__ C, int ldc,
    int n0, int koff, int nk,
    float* As, float* Bs, int tid)
{
    const int ty  = tid >> 5;
    const int tx  = tid & 31;
    const int ar  = tid >> 2;
    const int akc = (tid & 3) * 4;
    const int bkr = tid >> 4;
    const int bnc = (tid & 15) * 8;

    const float* Aptr = A + (size_t)ar * lda + koff + akc;
    const float* Bptr = B + (size_t)(koff + bkr) * ldb + n0 + bnc;
    const size_t bstep = (size_t)16 * ldb;

    float4 aR  = *(const float4*)Aptr;
    float4 bR0 = *(const float4*)Bptr;
    float4 bR1 = *(const float4*)(Bptr + 4);
    As[(akc+0)*64+ar] = aR.x; As[(akc+1)*64+ar] = aR.y;
    As[(akc+2)*64+ar] = aR.z; As[(akc+3)*64+ar] = aR.w;
    *(float4*)&Bs[bkr*128+bnc]   = bR0;
    *(float4*)&Bs[bkr*128+bnc+4] = bR1;
    __syncthreads();

    float acc[8][4];
#pragma unroll
    for (int i = 0; i < 8; i++)
#pragma unroll
        for (int j = 0; j < 4; j++) acc[i][j] = 0.f;

    for (int kt = 0; kt < nk; kt++) {
        const int cur = kt & 1, nxt = cur ^ 1;
        float* Ac = As + cur * 1024;
        float* Bc = Bs + cur * 2048;
        if (kt + 1 < nk) {
            aR = *(const float4*)(Aptr + (kt + 1) * 16);
            const float* bp = Bptr + (size_t)(kt + 1) * bstep;
            bR0 = *(const float4*)bp;
            bR1 = *(const float4*)(bp + 4);
        }
#pragma unroll
        for (int kk = 0; kk < 16; kk++) {
            float4 a0 = *(const float4*)&Ac[kk*64 + ty*8];
            float4 a1 = *(const float4*)&Ac[kk*64 + ty*8 + 4];
            float4 b  = *(const float4*)&Bc[kk*128 + tx*4];
            float av[8] = {a0.x,a0.y,a0.z,a0.w,a1.x,a1.y,a1.z,a1.w};
            float bv[4] = {b.x,b.y,b.z,b.w};
#pragma unroll
            for (int i = 0; i < 8; i++)
#pragma unroll
                for (int j = 0; j < 4; j++)
                    acc[i][j] = fmaf(av[i], bv[j], acc[i][j]);
        }
        if (kt + 1 < nk) {
            float* An = As + nxt * 1024;
            float* Bn = Bs + nxt * 2048;
            An[(akc+0)*64+ar] = aR.x; An[(akc+1)*64+ar] = aR.y;
            An[(akc+2)*64+ar] = aR.z; An[(akc+3)*64+ar] = aR.w;
            *(float4*)&Bn[bkr*128+bnc]   = bR0;
            *(float4*)&Bn[bkr*128+bnc+4] = bR1;
            __syncthreads();
        }
    }
#pragma unroll
    for (int i = 0; i < 8; i++) {
        float* crow = C + (size_t)(ty*8 + i) * ldc + n0 + tx*4;
        *(float4*)crow = make_float4(acc[i][0], acc[i][1], acc[i][2], acc[i][3]);
    }
}

// ============ persistent decode-loop kernel ============
__global__ void __launch_bounds__(256, 1)
decode_loop_kernel(const float* __restrict__ b_dec_att, const float* __restrict__ Wf,
                   const float* __restrict__ bf, const float* __restrict__ b_fbeta,
                   const float* __restrict__ emb, const int* __restrict__ captions,
                   const int* __restrict__ cap_len,
                   const float* __restrict__ b_ih, const float* __restrict__ b_hh,
                   const float* __restrict__ b_init_h, const float* __restrict__ b_init_c,
                   float* __restrict__ out)
{
    __shared__ float sgemm[2 * 16 * 64 + 2 * 16 * 128];  // 24KB, overlaid
    __shared__ float sdec[ATT];
    __shared__ float swf[ATT];
    __shared__ float sred[256];
    __shared__ float salpha[256];

    __half* sAh = (__half*)sgemm;
    __half* sBh = sAh + 64 * 40;

    const int bid = blockIdx.x;
    const int tid = threadIdx.x;
    unsigned gen = ld_acq(&g_bargen);

    // ---- pre-phase A: h0/c0 partials (64 blocks, fp32) ----
    if (bid < 64) {
        const int nt = bid & 7, z = bid >> 3;
        gemm_tile(g_mean, ENC, g_Winit, 1024,
                  g_ipart + (size_t)z * 64 * 1024, 1024,
                  nt * 128, z * 256, 16, sgemm, sgemm + 2048, tid);
    }
    gbar(gen);
    // ---- pre-phase B: reduce -> h16cur, c ----
    if (bid < 64) {
        const int b = bid;
#pragma unroll
        for (int jj = 0; jj < 4; jj++) {
            const int col = tid + jj * 256;
            float v = 0.f;
#pragma unroll
            for (int z = 0; z < ISPLIT; z++) v += g_ipart[(size_t)(z * BATCH + b) * 1024 + col];
            if (col < DEC) g_h16cur[b * DEC + col] = __float2half_rn(v + b_init_h[col]);
            else           g_c[b * DEC + (col - DEC)] = v + b_init_c[col - DEC];
        }
    }
    gbar(gen);

    for (int t = 0; t < TSTEPS; t++) {
        // ---- phase 1: hproj partials via HMMA (144 blocks) + emb->x16 (4 blocks) ----
        if (bid < 144) {
            const int nt = bid >> 2;      // 0..35
            const int z  = bid & 3;       // 0..3
            hmma_tile(g_h16cur, DEC, g_WhcatT, DEC,
                      g_hpart + (size_t)z * 64 * HCAT, HCAT,
                      nt * 128, z * 128, 4, nullptr, sAh, sBh, tid);
        } else {
            for (int b = bid - 144; b < BATCH; b += 4) {
                const int tok = captions[b * MAXLEN + t];
                if (tid < 128) {
                    float4 v = *(const float4*)&emb[(size_t)tok * EMBD + tid * 4];
                    __half2 h0 = __floats2half2_rn(v.x, v.y);
                    __half2 h1 = __floats2half2_rn(v.z, v.w);
                    uint2 u;
                    u.x = *(uint32_t*)&h0; u.y = *(uint32_t*)&h1;
                    *(uint2*)&g_x16[b * XDIM + tid * 4] = u;
                }
            }
        }
        gbar(gen);

        // ---- phase 2: attention scores e[b,p] (128 blocks) ----
        if (bid < 128) {
            const int b = bid >> 1, ph = bid & 1;
            for (int k = tid; k < ATT; k += 256) {
                float s = b_dec_att[k];
#pragma unroll
                for (int z = 0; z < HSPLIT; z++)
                    s += g_hpart[(size_t)(z * BATCH + b) * HCAT + k];
                sdec[k] = s;
                swf[k] = Wf[k];
            }
            __syncthreads();
            const int warp = tid >> 5, lane = tid & 31;
            const float bf0 = bf[0];
            const int pbase = ph * 98;
            for (int p = pbase + warp; p < pbase + 98; p += 8) {
                const float* ae = g_att_enc + ((size_t)(b * PIX + p)) * ATT;
                float acc = 0.f;
                for (int k = lane; k < ATT; k += 32)
                    acc += tanh_fast(ae[k] + sdec[k]) * swf[k];
#pragma unroll
                for (int o = 16; o; o >>= 1) acc += __shfl_down_sync(0xffffffffu, acc, o);
                if (lane == 0) g_e[b * PIX + p] = acc + bf0;
            }
        }
        gbar(gen);

        // ---- phase 3: softmax + awe + x16 build + alphas out (128 blocks) ----
        if (bid < 128) {
            const int b = bid >> 1, chunk = bid & 1;
            float v = (tid < PIX) ? g_e[b * PIX + tid] : -1e30f;
            sred[tid] = v; __syncthreads();
            for (int s = 128; s; s >>= 1) { if (tid < s) sred[tid] = fmaxf(sred[tid], sred[tid+s]); __syncthreads(); }
            const float mx = sred[0]; __syncthreads();
            const float ex = (tid < PIX) ? __expf(v - mx) : 0.f;
            sred[tid] = ex; __syncthreads();
            for (int s = 128; s; s >>= 1) { if (tid < s) sred[tid] += sred[tid+s]; __syncthreads(); }
            const float inv = 1.f / sred[0];
            const float a = ex * inv;
            salpha[tid] = a;
            if (chunk == 0 && tid < PIX) {
                const float m = (t < cap_len[b] - 1) ? 1.f : 0.f;
                out[ALPHA_OFF + (size_t)b * TSTEPS * PIX + (size_t)t * PIX + tid] = a * m;
            }
            __syncthreads();

            const int d = chunk * 1024 + tid * 4;
            float4 acc = make_float4(0,0,0,0);
            const __half* ep = g_enc_h + (size_t)b * PIX * ENC + d;
#pragma unroll 4
            for (int p = 0; p < PIX; p++) {
                const float al = salpha[p];
                uint2 r = *(const uint2*)(ep + (size_t)p * ENC);
                __half2 h0 = *(const __half2*)&r.x;
                __half2 h1 = *(const __half2*)&r.y;
                acc.x = fmaf(al, __low2float(h0),  acc.x);
                acc.y = fmaf(al, __high2float(h0), acc.y);
                acc.z = fmaf(al, __low2float(h1),  acc.z);
                acc.w = fmaf(al, __high2float(h1), acc.w);
            }
            float4 g = make_float4(b_fbeta[d], b_fbeta[d+1], b_fbeta[d+2], b_fbeta[d+3]);
#pragma unroll
            for (int z = 0; z < HSPLIT; z++) {
                float4 p4 = *(const float4*)&g_hpart[(size_t)(z * BATCH + b) * HCAT + DEC + d];
                g.x += p4.x; g.y += p4.y; g.z += p4.z; g.w += p4.w;
            }
            g.x = sigmoidf_(g.x); g.y = sigmoidf_(g.y); g.z = sigmoidf_(g.z); g.w = sigmoidf_(g.w);
            __half2 o0 = __floats2half2_rn(acc.x * g.x, acc.y * g.y);
            __half2 o1 = __floats2half2_rn(acc.z * g.z, acc.w * g.w);
            uint2 u; u.x = *(uint32_t*)&o0; u.y = *(uint32_t*)&o1;
            *(uint2*)&g_x16[b * XDIM + EMBD + d] = u;
        }
        gbar(gen);

        // ---- phase 4: gates partials via HMMA (128 blocks, split-K 8, Kc=320) ----
        if (bid < 128) {
            const int nt = bid & 15;
            const int z  = bid >> 4;
            hmma_tile(g_x16, XDIM, g_WihT, XDIM,
                      g_gpart + (size_t)z * 64 * (4 * DEC), 4 * DEC,
                      nt * 128, z * 320, 10, nullptr, sAh, sBh, tid);
        }
        gbar(gen);

        // ---- phase 5: LSTM update + h16 history (64 blocks) ----
        if (bid < 64) {
            const int b = bid;
#pragma unroll
            for (int jj = 0; jj < 2; jj++) {
                const int j = tid + jj * 256;
                float gv[4];
#pragma unroll
                for (int s = 0; s < 4; s++) {
                    const int col = s * DEC + j;
                    float v = b_ih[col] + b_hh[col];
#pragma unroll
                    for (int z = 0; z < GSPLIT; z++)
                        v += g_gpart[(size_t)(z * BATCH + b) * (4 * DEC) + col];
#pragma unroll
                    for (int z = 0; z < HSPLIT; z++)
                        v += g_hpart[(size_t)(z * BATCH + b) * HCAT + (DEC + ENC) + col];
                    gv[s] = v;
                }
                float h = __half2float(g_h16cur[b * DEC + j]);
                if (t < cap_len[b] - 1) {
                    const float c_old = g_c[b * DEC + j];
                    const float cn = sigmoidf_(gv[1]) * c_old + sigmoidf_(gv[0]) * tanhf(gv[2]);
                    g_c[b * DEC + j] = cn;
                    h = sigmoidf_(gv[3]) * tanhf(cn);
                    g_h16cur[b * DEC + j] = __float2half_rn(h);
                }
                g_h16[((size_t)t * BATCH + b) * DEC + j] = __float2half_rn(h);
            }
        }
        gbar(gen);
    }
}

// ============ prologue att_enc GEMM via HMMA ============
__global__ void __launch_bounds__(256)
attenc_mma_kernel(const float* __restrict__ b_enc_att)
{
    __shared__ __half sAh[64 * 40];
    __shared__ __half sBh[128 * 40];
    const int m0 = blockIdx.y * 64;
    const int n0 = blockIdx.x * 128;
    hmma_tile(g_enc_h + (size_t)m0 * ENC, ENC, g_WencT, ENC,
              g_att_enc + (size_t)m0 * ATT, ATT,
              n0, 0, ENC / 32, b_enc_att, sAh, sBh, threadIdx.x);
}

// ============ batched predictions via HMMA (bias + mask epilogue) ============
__global__ void __launch_bounds__(256)
preds_mma_kernel(const float* __restrict__ b_fc, const float* __restrict__ mask,
                 float* __restrict__ out)
{
    __shared__ __half sAh[64 * 40];
    __shared__ __half sBh[128 * 40];

    const int tid  = threadIdx.x;
    const int wid  = tid >> 5;
    const int lane = tid & 31;
    const int grp  = lane >> 2;
    const int tg   = lane & 3;
    const int wm   = wid >> 2;
    const int wn   = wid & 3;

    const int m0 = blockIdx.y * 64;
    const int n0 = blockIdx.x * 128;

    const int arow = tid >> 2;
    const int aseg = (tid & 3) * 8;

    const __half* Ap = g_h16  + (size_t)(m0 + arow) * DEC + aseg;
    const __half* Bp = g_WfcT + (size_t)(n0 + arow) * DEC + aseg;

    float c[2][4][4];
#pragma unroll
    for (int i = 0; i < 2; i++)
#pragma unroll
        for (int j = 0; j < 4; j++)
#pragma unroll
            for (int q = 0; q < 4; q++) c[i][j][q] = 0.f;

    for (int kt = 0; kt < DEC / 32; kt++) {
        const int kb = kt * 32;
        __syncthreads();
        *(uint4*)&sAh[arow * 40 + aseg]        = *(const uint4*)(Ap + kb);
        *(uint4*)&sBh[arow * 40 + aseg]        = *(const uint4*)(Bp + kb);
        *(uint4*)&sBh[(arow + 64) * 40 + aseg] = *(const uint4*)(Bp + (size_t)64 * DEC + kb);
        __syncthreads();

#pragma unroll
        for (int ks = 0; ks < 2; ks++) {
            const int k0 = ks * 16;
            uint32_t a[2][4];
#pragma unroll
            for (int mi = 0; mi < 2; mi++) {
                const int r = wm * 32 + mi * 16 + grp;
                a[mi][0] = *(const uint32_t*)&sAh[(r    ) * 40 + k0 + tg * 2];
                a[mi][1] = *(const uint32_t*)&sAh[(r + 8) * 40 + k0 + tg * 2];
                a[mi][2] = *(const uint32_t*)&sAh[(r    ) * 40 + k0 + tg * 2 + 8];
                a[mi][3] = *(const uint32_t*)&sAh[(r + 8) * 40 + k0 + tg * 2 + 8];
            }
#pragma unroll
            for (int ni = 0; ni < 4; ni++) {
                const int nr = wn * 32 + ni * 8 + grp;
                uint32_t b0 = *(const uint32_t*)&sBh[nr * 40 + k0 + tg * 2];
                uint32_t b1 = *(const uint32_t*)&sBh[nr * 40 + k0 + tg * 2 + 8];
#pragma unroll
                for (int mi = 0; mi < 2; mi++) {
                    asm volatile(
                        "mma.sync.aligned.m16n8k16.row.col.f32.f16.f16.f32 "
                        "{%0,%1,%2,%3}, {%4,%5,%6,%7}, {%8,%9}, {%0,%1,%2,%3};"
                        : "+f"(c[mi][ni][0]), "+f"(c[mi][ni][1]),
                          "+f"(c[mi][ni][2]), "+f"(c[mi][ni][3])
                        : "r"(a[mi][0]), "r"(a[mi][1]), "r"(a[mi][2]), "r"(a[mi][3]),
                          "r"(b0), "r"(b1));
                }
            }
        }
    }

#pragma unroll
    for (int mi = 0; mi < 2; mi++) {
#pragma unroll
        for (int hh = 0; hh < 2; hh++) {
            const int m = m0 + wm * 32 + mi * 16 + grp + hh * 8;
            const int tt = m >> 6, bb = m & 63;
            const float ms = mask[tt * BATCH + bb];
            float* orow = out + PRED_OFF + ((size_t)bb * TSTEPS + tt) * VOC;
#pragma unroll
            for (int ni = 0; ni < 4; ni++) {
                const int n = n0 + wn * 32 + ni * 8 + tg * 2;
                if (n + 1 < VOC) {
                    orow[n]     = (c[mi][ni][hh * 2]     + b_fc[n])     * ms;
                    orow[n + 1] = (c[mi][ni][hh * 2 + 1] + b_fc[n + 1]) * ms;
                } else if (n < VOC) {
                    orow[n] = (c[mi][ni][hh * 2] + b_fc[n]) * ms;
                }
            }
        }
    }
}

// ---------------- init: transposed fp16 weights, enc fp16, mask, int outputs ------
__global__ void init_kernel(const float* __restrict__ Wdec, const float* __restrict__ Wfbeta,
                            const float* __restrict__ Whh, const float* __restrict__ Wih,
                            const float* __restrict__ Wenc,
                            const float* __restrict__ Winith, const float* __restrict__ Winitc,
                            const float* __restrict__ Wfc, const float* __restrict__ enc,
                            const int* __restrict__ captions, const int* __restrict__ cap_len,
                            float* __restrict__ out)
{
    int idx = blockIdx.x * blockDim.x + threadIdx.x;
    int stride = gridDim.x * blockDim.x;
    // WhcatT[n][k]: n indexes [dec_att|fbeta|hh] output col, k indexes DEC
    for (int i = idx; i < HCAT * DEC; i += stride) {
        int n = i >> 9, k = i & 511;
        float v;
        if (n < DEC)              v = Wdec[k * DEC + n];
        else if (n < DEC + ENC)   v = Wfbeta[k * ENC + (n - DEC)];
        else                      v = Whh[k * (4 * DEC) + (n - DEC - ENC)];
        g_WhcatT[i] = __float2half_rn(v);
    }
    // WihT[n][k]: n in [0,2048), k in [0,2560)
    for (int i = idx; i < 4 * DEC * XDIM; i += stride) {
        int n = i / XDIM, k = i - n * XDIM;
        g_WihT[i] = __float2half_rn(Wih[(size_t)k * (4 * DEC) + n]);
    }
    // WencT[n][k]: n in [0,512), k in [0,2048)
    for (int i = idx; i < ATT * ENC; i += stride) {
        int n = i >> 11, k = i & 2047;
        g_WencT[i] = __float2half_rn(Wenc[(size_t)k * ATT + n]);
    }
    // WfcT[n][k], zero-padded
    for (int i = idx; i < NPAD * DEC; i += stride) {
        int n = i >> 9, k = i & 511;
        g_WfcT[i] = (n < VOC) ? __float2half_rn(Wfc[(size_t)k * VOC + n]) : __ushort_as_half(0);
    }
    // Winit fp32 [k][h0|c0]
    for (int i = idx; i < ENC * 1024; i += stride) {
        int k = i >> 10, j = i & 1023;
        g_Winit[i] = (j < DEC) ? Winith[k * DEC + j] : Winitc[k * DEC + (j - DEC)];
    }
    for (int i = idx; i < BATCH * PIX * ENC; i += stride)
        g_enc_h[i] = __float2half_rn(enc[i]);
    if (idx < TSTEPS * BATCH) {
        int t = idx / BATCH, b = idx - t * BATCH;
        g_mask[idx] = (t < cap_len[b] - 1) ? 1.f : 0.f;
    }
    if (idx < BATCH * MAXLEN) out[CAP_OFF + idx] = (float)captions[idx];
    if (idx < BATCH)          out[LEN_OFF + idx] = (float)(cap_len[idx] - 1);
}

__global__ void mean_kernel(const float* __restrict__ enc)
{
    int b = blockIdx.y;
    int d = blockIdx.x * 256 + threadIdx.x;
    const float* ep = enc + (size_t)b * PIX * ENC + d;
    float s = 0.f;
    for (int p = 0; p < PIX; p++) s += ep[(size_t)p * ENC];
    g_mean[b * ENC + d] = s * (1.f / (float)PIX);
}

// ---------------- host launcher ----------------
extern "C" void kernel_launch(void* const* d_in, const int* in_sizes, int n_in,
                              void* d_out, int out_size)
{
    const float* enc        = (const float*)d_in[0];
    const int*   captions   = (const int*)  d_in[1];
    const int*   cap_len    = (const int*)  d_in[2];
    const float* emb        = (const float*)d_in[3];
    const float* W_enc_att  = (const float*)d_in[4];
    const float* b_enc_att  = (const float*)d_in[5];
    const float* W_dec_att  = (const float*)d_in[6];
    const float* b_dec_att  = (const float*)d_in[7];
    const float* W_full_att = (const float*)d_in[8];
    const float* b_full_att = (const float*)d_in[9];
    const float* W_init_h   = (const float*)d_in[10];
    const float* b_init_h   = (const float*)d_in[11];
    const float* W_init_c   = (const float*)d_in[12];
    const float* b_init_c   = (const float*)d_in[13];
    const float* W_fbeta    = (const float*)d_in[14];
    const float* b_fbeta    = (const float*)d_in[15];
    const float* W_ih       = (const float*)d_in[16];
    const float* W_hh       = (const float*)d_in[17];
    const float* b_ih       = (const float*)d_in[18];
    const float* b_hh       = (const float*)d_in[19];
    const float* W_fc       = (const float*)d_in[20];
    const float* b_fc       = (const float*)d_in[21];
    float* out = (float*)d_out;
    (void)in_sizes; (void)n_in; (void)out_size;

    float* pmask;
    cudaGetSymbolAddress((void**)&pmask, g_mask);

    // 1: init (concat/transpose/fp16)
    init_kernel<<<4096, 256>>>(W_dec_att, W_fbeta, W_hh, W_ih, W_enc_att,
                               W_init_h, W_init_c, W_fc, enc, captions, cap_len, out);
    // 2: mean over pixels
    mean_kernel<<<dim3(ENC / 256, BATCH), 256>>>(enc);
    // 3: att_enc = enc @ W_enc_att + b (HMMA)
    attenc_mma_kernel<<<dim3(ATT / 128, (BATCH * PIX) / 64), 256>>>(b_enc_att);
    // 4: entire decode loop (persistent; includes h0/c0 pre-phase)
    decode_loop_kernel<<<NBLK, 256>>>(b_dec_att, W_full_att, b_full_att, b_fbeta,
                                      emb, captions, cap_len,
                                      b_ih, b_hh, b_init_h, b_init_c, out);
    // 5: all predictions (HMMA)
    preds_mma_kernel<<<dim3(NPAD / 128, MTOT / 64), 256>>>(b_fc, pmask, out);
}

// round 8
// speedup vs baseline: 6.0989x; 1.0607x over previous
#include <cuda_runtime.h>
#include <cuda_fp16.h>
#include <math.h>
#include <stdint.h>

// Problem constants
#define BATCH   64
#define PIX     196
#define ENC     2048
#define DEC     512
#define ATT     512
#define EMBD    512
#define VOC     10000
#define MAXLEN  52
#define TSTEPS  51
#define HCAT2   2560     // 512 dec_att | 2048 fbeta
#define XDIM2   3072     // emb 512 | awe 2048 | h 512
#define GDIM    2048     // 4*DEC

// Output layout (flattened tuple, float32)
#define PRED_OFF   0
#define CAP_OFF    32640000
#define LEN_OFF    32643328
#define ALPHA_OFF  32643392

#define HSPLIT 4         // hproj split-K
#define GSPLITB 8        // gates part-B split-K
#define ISPLIT 8         // h0c0 split-K

#define MTOT  (TSTEPS * BATCH)   // 3264
#define NPAD  10112              // 79*128 >= VOC
#define NBLK  148                // persistent grid

// ---------------- scratch ----------------
__device__ __align__(16) __half g_WhcatT[HCAT2 * DEC];    // [n][k]
__device__ __align__(16) __half g_WihT[GDIM * XDIM2];     // [n][k] (W_ih|W_hh)
__device__ __align__(16) __half g_WencT[ATT * ENC];       // [n][k]
__device__ __align__(16) __half g_WfcT[NPAD * DEC];       // [n][k]
__device__ __align__(16) __half g_WinitT[1024 * ENC];     // [n][k] (h0|c0)
__device__ __align__(16) __half g_enc_h[(BATCH * PIX + 8) * ENC]; // padded
__device__ __align__(16) __half g_mean16[BATCH * ENC];
__device__ __align__(16) __half g_h16cur[BATCH * DEC];
__device__ __align__(16) __half g_h16[MTOT * DEC];
__device__ __align__(16) __half g_x16[BATCH * XDIM2];
__device__ float  g_mask[TSTEPS * BATCH];
__device__ float  g_c[BATCH * DEC];
__device__ float  g_att_enc[BATCH * PIX * ATT];
__device__ float  g_hpart[HSPLIT * BATCH * HCAT2];
__device__ float  g_gpartA[2 * BATCH * GDIM];
__device__ float  g_gpartB[GSPLITB * BATCH * GDIM];
__device__ float  g_ipart[ISPLIT * BATCH * 1024];
__device__ float  g_e[BATCH * PIX];

// grid barrier state
__device__ unsigned g_barcnt = 0;
__device__ unsigned g_bargen = 0;

__device__ __forceinline__ float sigmoidf_(float x) { return 1.f / (1.f + __expf(-x)); }
__device__ __forceinline__ float tanh_fast(float x) {
    float y; asm("tanh.approx.f32 %0, %1;" : "=f"(y) : "f"(x)); return y;
}
__device__ __forceinline__ unsigned ld_acq(const unsigned* p) {
    unsigned v;
    asm volatile("ld.acquire.gpu.u32 %0, [%1];" : "=r"(v) : "l"(p) : "memory");
    return v;
}
__device__ __forceinline__ void gbar(unsigned& gen) {
    __syncthreads();
    if (threadIdx.x == 0) {
        __threadfence();
        unsigned arrived = atomicAdd(&g_barcnt, 1u);
        if (arrived == NBLK - 1) {
            g_barcnt = 0;
            __threadfence();
            atomicAdd(&g_bargen, 1u);
        } else {
            while (ld_acq(&g_bargen) == gen) { __nanosleep(16); }
        }
    }
    gen++;
    __syncthreads();
}

// ---------------- HMMA 64x128 tile (fp16 in, fp32 acc) ----------------
// C[0..63][n0..n0+127] = A[64 rows, lda] x B[n rows, ldb] over K [koff, koff+32*nsteps)
__device__ __forceinline__ void hmma_tile(
    const __half* __restrict__ Ag, int lda,
    const __half* __restrict__ Bg, int ldb,
    float* __restrict__ Cg, int ldc,
    int n0, int koff, int nsteps,
    const float* __restrict__ bias,
    __half* sAh, __half* sBh, int tid)
{
    const int wid  = tid >> 5;
    const int lane = tid & 31;
    const int grp  = lane >> 2;
    const int tg   = lane & 3;
    const int wm   = wid >> 2;
    const int wn   = wid & 3;

    const int arow = tid >> 2;            // 0..63
    const int aseg = (tid & 3) * 8;

    const __half* Ap = Ag + (size_t)arow * lda + koff + aseg;
    const __half* Bp = Bg + (size_t)(n0 + arow) * ldb + koff + aseg;

    float c[2][4][4];
#pragma unroll
    for (int i = 0; i < 2; i++)
#pragma unroll
        for (int j = 0; j < 4; j++)
#pragma unroll
            for (int q = 0; q < 4; q++) c[i][j][q] = 0.f;

    for (int kt = 0; kt < nsteps; kt++) {
        const int kb = kt * 32;
        __syncthreads();
        *(uint4*)&sAh[arow * 40 + aseg]        = *(const uint4*)(Ap + kb);
        *(uint4*)&sBh[arow * 40 + aseg]        = *(const uint4*)(Bp + kb);
        *(uint4*)&sBh[(arow + 64) * 40 + aseg] = *(const uint4*)(Bp + (size_t)64 * ldb + kb);
        __syncthreads();

#pragma unroll
        for (int ks = 0; ks < 2; ks++) {
            const int k0 = ks * 16;
            uint32_t a[2][4];
#pragma unroll
            for (int mi = 0; mi < 2; mi++) {
                const int r = wm * 32 + mi * 16 + grp;
                a[mi][0] = *(const uint32_t*)&sAh[(r    ) * 40 + k0 + tg * 2];
                a[mi][1] = *(const uint32_t*)&sAh[(r + 8) * 40 + k0 + tg * 2];
                a[mi][2] = *(const uint32_t*)&sAh[(r    ) * 40 + k0 + tg * 2 + 8];
                a[mi][3] = *(const uint32_t*)&sAh[(r + 8) * 40 + k0 + tg * 2 + 8];
            }
#pragma unroll
            for (int ni = 0; ni < 4; ni++) {
                const int nr = wn * 32 + ni * 8 + grp;
                uint32_t b0 = *(const uint32_t*)&sBh[nr * 40 + k0 + tg * 2];
                uint32_t b1 = *(const uint32_t*)&sBh[nr * 40 + k0 + tg * 2 + 8];
#pragma unroll
                for (int mi = 0; mi < 2; mi++) {
                    asm volatile(
                        "mma.sync.aligned.m16n8k16.row.col.f32.f16.f16.f32 "
                        "{%0,%1,%2,%3}, {%4,%5,%6,%7}, {%8,%9}, {%0,%1,%2,%3};"
                        : "+f"(c[mi][ni][0]), "+f"(c[mi][ni][1]),
                          "+f"(c[mi][ni][2]), "+f"(c[mi][ni][3])
                        : "r"(a[mi][0]), "r"(a[mi][1]), "r"(a[mi][2]), "r"(a[mi][3]),
                          "r"(b0), "r"(b1));
                }
            }
        }
    }

#pragma unroll
    for (int mi = 0; mi < 2; mi++) {
#pragma unroll
        for (int hh = 0; hh < 2; hh++) {
            const int row = wm * 32 + mi * 16 + grp + hh * 8;
            float* crow = Cg + (size_t)row * ldc;
#pragma unroll
            for (int ni = 0; ni < 4; ni++) {
                const int col = n0 + wn * 32 + ni * 8 + tg * 2;
                float v0 = c[mi][ni][hh * 2];
                float v1 = c[mi][ni][hh * 2 + 1];
                if (bias) { v0 += bias[col]; v1 += bias[col + 1]; }
                crow[col]     = v0;
                crow[col + 1] = v1;
            }
        }
    }
}

// ============ persistent decode-loop kernel ============
__global__ void __launch_bounds__(256, 1)
decode_loop_kernel(const float* __restrict__ b_dec_att, const float* __restrict__ Wf,
                   const float* __restrict__ bf, const float* __restrict__ b_fbeta,
                   const float* __restrict__ emb, const int* __restrict__ captions,
                   const int* __restrict__ cap_len,
                   const float* __restrict__ b_ih, const float* __restrict__ b_hh,
                   const float* __restrict__ b_init_h, const float* __restrict__ b_init_c,
                   float* __restrict__ out)
{
    __shared__ __half sAh[64 * 40];
    __shared__ __half sBh[128 * 40];
    __shared__ float sdec[ATT];
    __shared__ float swf[ATT];
    __shared__ float sred[256];
    __shared__ float salpha[256];

    const int bid = blockIdx.x;
    const int tid = threadIdx.x;
    unsigned gen = ld_acq(&g_bargen);

    // ---- pre-phase A: h0/c0 partials via HMMA (64 blocks) ----
    if (bid < 64) {
        const int nt = bid & 7, z = bid >> 3;
        hmma_tile(g_mean16, ENC, g_WinitT, ENC,
                  g_ipart + (size_t)z * 64 * 1024, 1024,
                  nt * 128, z * 256, 8, nullptr, sAh, sBh, tid);
    }
    gbar(gen);
    // ---- pre-phase B: reduce -> h0 (h16cur + x slot), c0; prefetch emb for t=0 ----
    if (bid < 64) {
        const int b = bid;
#pragma unroll
        for (int jj = 0; jj < 4; jj++) {
            const int col = tid + jj * 256;
            float v = 0.f;
#pragma unroll
            for (int z = 0; z < ISPLIT; z++) v += g_ipart[(size_t)(z * BATCH + b) * 1024 + col];
            if (col < DEC) {
                __half hv = __float2half_rn(v + b_init_h[col]);
                g_h16cur[b * DEC + col] = hv;
                g_x16[b * XDIM2 + EMBD + ENC + col] = hv;
            } else {
                g_c[b * DEC + (col - DEC)] = v + b_init_c[col - DEC];
            }
        }
        // emb prefetch for step 0
        const int tok = captions[b * MAXLEN + 0];
        if (tid < 256) {
            float2 v = *(const float2*)&emb[(size_t)tok * EMBD + tid * 2];
            __half2 h2 = __floats2half2_rn(v.x, v.y);
            *(__half2*)&g_x16[b * XDIM2 + tid * 2] = h2;
        }
    }
    gbar(gen);

    for (int t = 0; t < TSTEPS; t++) {
        // ---- phase 1: hproj partials (80 blocks) + gates part-A over emb|h (32 blocks) ----
        if (bid < 80) {
            const int nt = bid / HSPLIT;          // 0..19
            const int z  = bid - nt * HSPLIT;     // 0..3
            hmma_tile(g_h16cur, DEC, g_WhcatT, DEC,
                      g_hpart + (size_t)z * 64 * HCAT2, HCAT2,
                      nt * 128, z * 128, 4, nullptr, sAh, sBh, tid);
        } else if (bid < 112) {
            const int idx = bid - 80;
            const int nt  = idx & 15;             // 0..15
            const int seg = idx >> 4;             // 0: emb K[0,512), 1: h K[2560,3072)
            hmma_tile(g_x16, XDIM2, g_WihT, XDIM2,
                      g_gpartA + (size_t)seg * 64 * GDIM, GDIM,
                      nt * 128, seg ? (EMBD + ENC) : 0, 16, nullptr, sAh, sBh, tid);
        }
        gbar(gen);

        // ---- phase 2: attention scores e[b,p] (128 blocks) ----
        if (bid < 128) {
            const int b = bid >> 1, ph = bid & 1;
            for (int k = tid; k < ATT; k += 256) {
                float s = b_dec_att[k];
#pragma unroll
                for (int z = 0; z < HSPLIT; z++)
                    s += g_hpart[(size_t)(z * BATCH + b) * HCAT2 + k];
                sdec[k] = s;
                swf[k] = Wf[k];
            }
            __syncthreads();
            const int warp = tid >> 5, lane = tid & 31;
            const float bf0 = bf[0];
            const int pbase = ph * 98;
            for (int p = pbase + warp; p < pbase + 98; p += 8) {
                const float* ae = g_att_enc + ((size_t)(b * PIX + p)) * ATT;
                float acc = 0.f;
#pragma unroll
                for (int kk = 0; kk < 16; kk++) {
                    const int k = lane + kk * 32;
                    acc += tanh_fast(ae[k] + sdec[k]) * swf[k];
                }
#pragma unroll
                for (int o = 16; o; o >>= 1) acc += __shfl_down_sync(0xffffffffu, acc, o);
                if (lane == 0) g_e[b * PIX + p] = acc + bf0;
            }
        }
        gbar(gen);

        // ---- phase 3: softmax + awe + x16 awe-slot + alphas out (128 blocks) ----
        if (bid < 128) {
            const int b = bid >> 1, chunk = bid & 1;
            float v = (tid < PIX) ? g_e[b * PIX + tid] : -1e30f;
            sred[tid] = v; __syncthreads();
            for (int s = 128; s; s >>= 1) { if (tid < s) sred[tid] = fmaxf(sred[tid], sred[tid+s]); __syncthreads(); }
            const float mx = sred[0]; __syncthreads();
            const float ex = (tid < PIX) ? __expf(v - mx) : 0.f;
            sred[tid] = ex; __syncthreads();
            for (int s = 128; s; s >>= 1) { if (tid < s) sred[tid] += sred[tid+s]; __syncthreads(); }
            const float inv = 1.f / sred[0];
            const float a = ex * inv;            // 0 for tid >= PIX
            salpha[tid] = a;
            if (chunk == 0 && tid < PIX) {
                const float m = (t < cap_len[b] - 1) ? 1.f : 0.f;
                out[ALPHA_OFF + (size_t)b * TSTEPS * PIX + (size_t)t * PIX + tid] = a * m;
            }
            __syncthreads();

            const int d = chunk * 1024 + tid * 4;
            float4 acc = make_float4(0,0,0,0);
            const __half* ep = g_enc_h + (size_t)b * PIX * ENC + d;
#pragma unroll 8
            for (int p = 0; p < 200; p++) {       // padded; alpha[196..200)=0
                const float al = salpha[p];
                uint2 r = *(const uint2*)(ep + (size_t)p * ENC);
                __half2 h0 = *(const __half2*)&r.x;
                __half2 h1 = *(const __half2*)&r.y;
                acc.x = fmaf(al, __low2float(h0),  acc.x);
                acc.y = fmaf(al, __high2float(h0), acc.y);
                acc.z = fmaf(al, __low2float(h1),  acc.z);
                acc.w = fmaf(al, __high2float(h1), acc.w);
            }
            float4 g = make_float4(b_fbeta[d], b_fbeta[d+1], b_fbeta[d+2], b_fbeta[d+3]);
#pragma unroll
            for (int z = 0; z < HSPLIT; z++) {
                float4 p4 = *(const float4*)&g_hpart[(size_t)(z * BATCH + b) * HCAT2 + DEC + d];
                g.x += p4.x; g.y += p4.y; g.z += p4.z; g.w += p4.w;
            }
            g.x = sigmoidf_(g.x); g.y = sigmoidf_(g.y); g.z = sigmoidf_(g.z); g.w = sigmoidf_(g.w);
            __half2 o0 = __floats2half2_rn(acc.x * g.x, acc.y * g.y);
            __half2 o1 = __floats2half2_rn(acc.z * g.z, acc.w * g.w);
            uint2 u; u.x = *(uint32_t*)&o0; u.y = *(uint32_t*)&o1;
            *(uint2*)&g_x16[b * XDIM2 + EMBD + d] = u;
        }
        gbar(gen);

        // ---- phase 4: gates part-B over awe K[512,2560) (128 blocks, split-K 8) ----
        if (bid < 128) {
            const int nt = bid & 15;
            const int z  = bid >> 4;
            hmma_tile(g_x16, XDIM2, g_WihT, XDIM2,
                      g_gpartB + (size_t)z * 64 * GDIM, GDIM,
                      nt * 128, EMBD + z * 256, 8, nullptr, sAh, sBh, tid);
        }
        gbar(gen);

        // ---- phase 5: LSTM update + history + x h-slot + emb prefetch t+1 (64 blocks) ----
        if (bid < 64) {
            const int b = bid;
#pragma unroll
            for (int jj = 0; jj < 2; jj++) {
                const int j = tid + jj * 256;
                float gv[4];
#pragma unroll
                for (int s = 0; s < 4; s++) {
                    const int col = s * DEC + j;
                    float v = b_ih[col] + b_hh[col]
                            + g_gpartA[(size_t)b * GDIM + col]
                            + g_gpartA[(size_t)(BATCH + b) * GDIM + col];
#pragma unroll
                    for (int z = 0; z < GSPLITB; z++)
                        v += g_gpartB[(size_t)(z * BATCH + b) * GDIM + col];
                    gv[s] = v;
                }
                float h = __half2float(g_h16cur[b * DEC + j]);
                if (t < cap_len[b] - 1) {
                    const float c_old = g_c[b * DEC + j];
                    const float cn = sigmoidf_(gv[1]) * c_old + sigmoidf_(gv[0]) * tanhf(gv[2]);
                    g_c[b * DEC + j] = cn;
                    h = sigmoidf_(gv[3]) * tanhf(cn);
                }
                __half hv = __float2half_rn(h);
                g_h16cur[b * DEC + j] = hv;
                g_x16[b * XDIM2 + EMBD + ENC + j] = hv;
                g_h16[((size_t)t * BATCH + b) * DEC + j] = hv;
            }
            if (t + 1 < TSTEPS) {
                const int tok = captions[b * MAXLEN + t + 1];
                float2 v = *(const float2*)&emb[(size_t)tok * EMBD + tid * 2];
                __half2 h2 = __floats2half2_rn(v.x, v.y);
                *(__half2*)&g_x16[b * XDIM2 + tid * 2] = h2;
            }
        }
        gbar(gen);
    }
}

// ============ prologue att_enc GEMM via HMMA ============
__global__ void __launch_bounds__(256)
attenc_mma_kernel(const float* __restrict__ b_enc_att)
{
    __shared__ __half sAh[64 * 40];
    __shared__ __half sBh[128 * 40];
    const int m0 = blockIdx.y * 64;
    const int n0 = blockIdx.x * 128;
    hmma_tile(g_enc_h + (size_t)m0 * ENC, ENC, g_WencT, ENC,
              g_att_enc + (size_t)m0 * ATT, ATT,
              n0, 0, ENC / 32, b_enc_att, sAh, sBh, threadIdx.x);
}

// ============ batched predictions via HMMA ============
__global__ void __launch_bounds__(256)
preds_mma_kernel(const float* __restrict__ b_fc, const float* __restrict__ mask,
                 float* __restrict__ out)
{
    __shared__ __half sAh[64 * 40];
    __shared__ __half sBh[128 * 40];

    const int tid  = threadIdx.x;
    const int wid  = tid >> 5;
    const int lane = tid & 31;
    const int grp  = lane >> 2;
    const int tg   = lane & 3;
    const int wm   = wid >> 2;
    const int wn   = wid & 3;

    const int m0 = blockIdx.y * 64;
    const int n0 = blockIdx.x * 128;

    const int arow = tid >> 2;
    const int aseg = (tid & 3) * 8;

    const __half* Ap = g_h16  + (size_t)(m0 + arow) * DEC + aseg;
    const __half* Bp = g_WfcT + (size_t)(n0 + arow) * DEC + aseg;

    float c[2][4][4];
#pragma unroll
    for (int i = 0; i < 2; i++)
#pragma unroll
        for (int j = 0; j < 4; j++)
#pragma unroll
            for (int q = 0; q < 4; q++) c[i][j][q] = 0.f;

    for (int kt = 0; kt < DEC / 32; kt++) {
        const int kb = kt * 32;
        __syncthreads();
        *(uint4*)&sAh[arow * 40 + aseg]        = *(const uint4*)(Ap + kb);
        *(uint4*)&sBh[arow * 40 + aseg]        = *(const uint4*)(Bp + kb);
        *(uint4*)&sBh[(arow + 64) * 40 + aseg] = *(const uint4*)(Bp + (size_t)64 * DEC + kb);
        __syncthreads();

#pragma unroll
        for (int ks = 0; ks < 2; ks++) {
            const int k0 = ks * 16;
            uint32_t a[2][4];
#pragma unroll
            for (int mi = 0; mi < 2; mi++) {
                const int r = wm * 32 + mi * 16 + grp;
                a[mi][0] = *(const uint32_t*)&sAh[(r    ) * 40 + k0 + tg * 2];
                a[mi][1] = *(const uint32_t*)&sAh[(r + 8) * 40 + k0 + tg * 2];
                a[mi][2] = *(const uint32_t*)&sAh[(r    ) * 40 + k0 + tg * 2 + 8];
                a[mi][3] = *(const uint32_t*)&sAh[(r + 8) * 40 + k0 + tg * 2 + 8];
            }
#pragma unroll
            for (int ni = 0; ni < 4; ni++) {
                const int nr = wn * 32 + ni * 8 + grp;
                uint32_t b0 = *(const uint32_t*)&sBh[nr * 40 + k0 + tg * 2];
                uint32_t b1 = *(const uint32_t*)&sBh[nr * 40 + k0 + tg * 2 + 8];
#pragma unroll
                for (int mi = 0; mi < 2; mi++) {
                    asm volatile(
                        "mma.sync.aligned.m16n8k16.row.col.f32.f16.f16.f32 "
                        "{%0,%1,%2,%3}, {%4,%5,%6,%7}, {%8,%9}, {%0,%1,%2,%3};"
                        : "+f"(c[mi][ni][0]), "+f"(c[mi][ni][1]),
                          "+f"(c[mi][ni][2]), "+f"(c[mi][ni][3])
                        : "r"(a[mi][0]), "r"(a[mi][1]), "r"(a[mi][2]), "r"(a[mi][3]),
                          "r"(b0), "r"(b1));
                }
            }
        }
    }

#pragma unroll
    for (int mi = 0; mi < 2; mi++) {
#pragma unroll
        for (int hh = 0; hh < 2; hh++) {
            const int m = m0 + wm * 32 + mi * 16 + grp + hh * 8;
            const int tt = m >> 6, bb = m & 63;
            const float ms = mask[tt * BATCH + bb];
            float* orow = out + PRED_OFF + ((size_t)bb * TSTEPS + tt) * VOC;
#pragma unroll
            for (int ni = 0; ni < 4; ni++) {
                const int n = n0 + wn * 32 + ni * 8 + tg * 2;
                if (n + 1 < VOC) {
                    orow[n]     = (c[mi][ni][hh * 2]     + b_fc[n])     * ms;
                    orow[n + 1] = (c[mi][ni][hh * 2 + 1] + b_fc[n + 1]) * ms;
                } else if (n < VOC) {
                    orow[n] = (c[mi][ni][hh * 2] + b_fc[n]) * ms;
                }
            }
        }
    }
}

// ---------------- init ----------------
__global__ void init_kernel(const float* __restrict__ Wdec, const float* __restrict__ Wfbeta,
                            const float* __restrict__ Whh, const float* __restrict__ Wih,
                            const float* __restrict__ Wenc,
                            const float* __restrict__ Winith, const float* __restrict__ Winitc,
                            const float* __restrict__ Wfc, const float* __restrict__ enc,
                            const int* __restrict__ captions, const int* __restrict__ cap_len,
                            float* __restrict__ out)
{
    int idx = blockIdx.x * blockDim.x + threadIdx.x;
    int stride = gridDim.x * blockDim.x;
    // WhcatT[n][k], n<2560
    for (int i = idx; i < HCAT2 * DEC; i += stride) {
        int n = i >> 9, k = i & 511;
        float v = (n < DEC) ? Wdec[k * DEC + n] : Wfbeta[k * ENC + (n - DEC)];
        g_WhcatT[i] = __float2half_rn(v);
    }
    // WihT[n][k], k<3072: k<2560 -> Wih, else Whh
    for (int i = idx; i < GDIM * XDIM2; i += stride) {
        int n = i / XDIM2, k = i - n * XDIM2;
        float v = (k < EMBD + ENC) ? Wih[(size_t)k * GDIM + n]
                                   : Whh[(size_t)(k - EMBD - ENC) * GDIM + n];
        g_WihT[i] = __float2half_rn(v);
    }
    // WencT[n][k]
    for (int i = idx; i < ATT * ENC; i += stride) {
        int n = i >> 11, k = i & 2047;
        g_WencT[i] = __float2half_rn(Wenc[(size_t)k * ATT + n]);
    }
    // WfcT[n][k], padded
    for (int i = idx; i < NPAD * DEC; i += stride) {
        int n = i >> 9, k = i & 511;
        g_WfcT[i] = (n < VOC) ? __float2half_rn(Wfc[(size_t)k * VOC + n]) : __ushort_as_half(0);
    }
    // WinitT[n][k]
    for (int i = idx; i < 1024 * ENC; i += stride) {
        int n = i >> 11, k = i & 2047;
        float v = (n < DEC) ? Winith[k * DEC + n] : Winitc[k * DEC + (n - DEC)];
        g_WinitT[i] = __float2half_rn(v);
    }
    for (int i = idx; i < BATCH * PIX * ENC; i += stride)
        g_enc_h[i] = __float2half_rn(enc[i]);
    // zero the pad rows
    for (int i = idx; i < 8 * ENC; i += stride)
        g_enc_h[BATCH * PIX * ENC + i] = __ushort_as_half(0);
    if (idx < TSTEPS * BATCH) {
        int t = idx / BATCH, b = idx - t * BATCH;
        g_mask[idx] = (t < cap_len[b] - 1) ? 1.f : 0.f;
    }
    if (idx < BATCH * MAXLEN) out[CAP_OFF + idx] = (float)captions[idx];
    if (idx < BATCH)          out[LEN_OFF + idx] = (float)(cap_len[idx] - 1);
}

__global__ void mean_kernel(const float* __restrict__ enc)
{
    int b = blockIdx.y;
    int d = blockIdx.x * 256 + threadIdx.x;
    const float* ep = enc + (size_t)b * PIX * ENC + d;
    float s = 0.f;
    for (int p = 0; p < PIX; p++) s += ep[(size_t)p * ENC];
    g_mean16[b * ENC + d] = __float2half_rn(s * (1.f / (float)PIX));
}

// ---------------- host launcher ----------------
extern "C" void kernel_launch(void* const* d_in, const int* in_sizes, int n_in,
                              void* d_out, int out_size)
{
    const float* enc        = (const float*)d_in[0];
    const int*   captions   = (const int*)  d_in[1];
    const int*   cap_len    = (const int*)  d_in[2];
    const float* emb        = (const float*)d_in[3];
    const float* W_enc_att  = (const float*)d_in[4];
    const float* b_enc_att  = (const float*)d_in[5];
    const float* W_dec_att  = (const float*)d_in[6];
    const float* b_dec_att  = (const float*)d_in[7];
    const float* W_full_att = (const float*)d_in[8];
    const float* b_full_att = (const float*)d_in[9];
    const float* W_init_h   = (const float*)d_in[10];
    const float* b_init_h   = (const float*)d_in[11];
    const float* W_init_c   = (const float*)d_in[12];
    const float* b_init_c   = (const float*)d_in[13];
    const float* W_fbeta    = (const float*)d_in[14];
    const float* b_fbeta    = (const float*)d_in[15];
    const float* W_ih       = (const float*)d_in[16];
    const float* W_hh       = (const float*)d_in[17];
    const float* b_ih       = (const float*)d_in[18];
    const float* b_hh       = (const float*)d_in[19];
    const float* W_fc       = (const float*)d_in[20];
    const float* b_fc       = (const float*)d_in[21];
    float* out = (float*)d_out;
    (void)in_sizes; (void)n_in; (void)out_size;

    float* pmask;
    cudaGetSymbolAddress((void**)&pmask, g_mask);

    // 1: init (concat/transpose/fp16)
    init_kernel<<<4096, 256>>>(W_dec_att, W_fbeta, W_hh, W_ih, W_enc_att,
                               W_init_h, W_init_c, W_fc, enc, captions, cap_len, out);
    // 2: mean over pixels (fp16 out)
    mean_kernel<<<dim3(ENC / 256, BATCH), 256>>>(enc);
    // 3: att_enc = enc @ W_enc_att + b (HMMA)
    attenc_mma_kernel<<<dim3(ATT / 128, (BATCH * PIX) / 64), 256>>>(b_enc_att);
    // 4: entire decode loop (persistent)
    decode_loop_kernel<<<NBLK, 256>>>(b_dec_att, W_full_att, b_full_att, b_fbeta,
                                      emb, captions, cap_len,
                                      b_ih, b_hh, b_init_h, b_init_c, out);
    // 5: all predictions (HMMA)
    preds_mma_kernel<<<dim3(NPAD / 128, MTOT / 64), 256>>>(b_fc, pmask, out);
}